// round 8
// baseline (speedup 1.0000x reference)
#include <cuda_runtime.h>
#include <cstdint>
#include <cstddef>

namespace {
constexpr int Bn = 32, Tn = 1024, INn = 1536, Dn = 768;
constexpr int Mn = Bn * Tn;  // 32768
}

// Scratch (static __device__ globals: allocation-free rule)
__device__ __align__(256) float g_X [(size_t)Mn * INn];
__device__ __align__(256) float g_H [(size_t)Mn * INn];
__device__ __align__(256) float g_U [(size_t)Mn * Dn];
__device__ __align__(256) float g_E [(size_t)Mn * Dn];
__device__ __align__(256) float g_XE[(size_t)Mn * Dn];
__device__ __align__(256) float g_YE[(size_t)Mn * Dn];
__device__ __align__(256) float g_W1[(size_t)INn * INn];
__device__ __align__(256) float g_W2[(size_t)Dn * INn];
__device__ __align__(256) float g_W3[(size_t)Dn * Dn];
__device__ __align__(256) float g_W4[(size_t)Dn * Dn];
__device__ __align__(256) float g_W5[(size_t)Dn * Dn];
__device__ __align__(256) float g_YB[Bn * Dn];
__device__ __align__(256) float g_UP[Mn];
__device__ __align__(256) float g_INX[Mn];
__device__ __align__(256) float g_SC[Mn];

// ---------------------------------------------------------------------------
// helpers
// ---------------------------------------------------------------------------
__device__ __forceinline__ uint32_t smem_u32(const void* p) {
    uint32_t a;
    asm("{ .reg .u64 t; cvta.to.shared.u64 t, %1; cvt.u32.u64 %0, t; }" : "=r"(a) : "l"(p));
    return a;
}
__device__ __forceinline__ void cp16(float* s, const float* g) {
    uint32_t sa = (uint32_t)__cvta_generic_to_shared(s);
    asm volatile("cp.async.cg.shared.global [%0], [%1], 16;\n" :: "r"(sa), "l"(g));
}
__device__ __forceinline__ void cp_commit() { asm volatile("cp.async.commit_group;\n"); }
template <int NW> __device__ __forceinline__ void cp_wait() {
    asm volatile("cp.async.wait_group %0;\n" :: "n"(NW));
}
__device__ __forceinline__ uint32_t f2tf(float x) {
    uint32_t r;
    asm("cvt.rna.tf32.f32 %0, %1;\n" : "=r"(r) : "f"(x));
    return r;
}
__device__ __forceinline__ void mma8(float* c, const uint32_t* a, const uint32_t* b) {
    asm volatile(
        "mma.sync.aligned.m16n8k8.row.col.f32.tf32.tf32.f32 "
        "{%0,%1,%2,%3}, {%4,%5,%6,%7}, {%8,%9}, {%0,%1,%2,%3};\n"
        : "+f"(c[0]), "+f"(c[1]), "+f"(c[2]), "+f"(c[3])
        : "r"(a[0]), "r"(a[1]), "r"(a[2]), "r"(a[3]), "r"(b[0]), "r"(b[1]));
}
__device__ __forceinline__ void ldsm4(uint32_t* r, uint32_t addr) {
    asm volatile("ldmatrix.sync.aligned.m8n8.x4.shared.b16 {%0,%1,%2,%3}, [%4];"
                 : "=r"(r[0]), "=r"(r[1]), "=r"(r[2]), "=r"(r[3]) : "r"(addr));
}

__global__ void round_k(const float4* __restrict__ src, float4* __restrict__ dst, int n4)
{
    int i = blockIdx.x * 256 + threadIdx.x;
    if (i >= n4) return;
    float4 v = src[i];
    v.x = __uint_as_float(f2tf(v.x)); v.y = __uint_as_float(f2tf(v.y));
    v.z = __uint_as_float(f2tf(v.z)); v.w = __uint_as_float(f2tf(v.w));
    dst[i] = v;
}

// ---------------------------------------------------------------------------
// GEMM: C[M,N] = A[M,K] @ W[N,K]^T + bias[N], optional relu / output rounding.
// Inputs tf32-valued. CTA 128x128x32, 128 threads, 4 warps 2(m)x2(n), warp
// tile 64x64, m16n8k8 tf32 via ldmatrix.x4, double-buffered cp.async.
// 3 CTAs/SM (12 warps): regs capped at 170 -> B frags resident (16 regs),
// A frags streamed per-mf (4 regs live).
// SMEM floats: [A st0 4096][A st1 4096][B st0 4096][B st1 4096] = 64 KB.
// ---------------------------------------------------------------------------
template <bool RELU, bool ROUND>
__global__ __launch_bounds__(128, 3) void gemm_tf32(
    const float* __restrict__ A, const float* __restrict__ W,
    const float* __restrict__ bias, float* __restrict__ C,
    int N, int K)
{
    extern __shared__ float smem[];
    const int tid  = threadIdx.x;
    const int lane = tid & 31, wrp = tid >> 5;
    const int wm = wrp >> 1, wn = wrp & 1;          // 2 x 2 warp grid
    const int m0 = blockIdx.y * 128, n0 = blockIdx.x * 128;

    // loader: thread -> col-group c4 (0..7), base row rb (0..15), rows rb+16p
    const int c4 = tid & 7, rb = tid >> 3;
    const int soff = rb * 32 + ((c4 ^ (rb & 7)) << 2);   // (rb+16p)&7 == rb&7
    const float* gA = A + (size_t)(m0 + rb) * K + c4 * 4;
    const float* gW = W + (size_t)(n0 + rb) * K + c4 * 4;

    // ldmatrix per-lane geometry
    const uint32_t smb = smem_u32(smem);
    const int s7 = lane & 7;
    const int half  = (lane >> 3) & 1;   // A: +8 rows for matrices 1,3
    const int koffA = lane >> 4;         // A: +1 col4 for matrices 2,3
    const int khB   = (lane >> 3) & 1;   // B: k-half within nf pair
    const int nfoB  = (lane >> 4) & 1;   // B: second nf of the pair
    const uint32_t baseA = (uint32_t)(wm * 64 + half * 8 + s7) * 128u;   // + mf*2048
    const uint32_t baseB = (uint32_t)(wn * 64 + nfoB * 8 + s7) * 128u;   // + j*2048

    float acc[4][8][4];
    #pragma unroll
    for (int i = 0; i < 4; i++)
        #pragma unroll
        for (int j = 0; j < 8; j++)
            #pragma unroll
            for (int q = 0; q < 4; q++) acc[i][j][q] = 0.f;

    const int kiters = K >> 5;

    #pragma unroll
    for (int p = 0; p < 8; p++) {
        cp16(&smem[soff + p * 512],        gA + (size_t)p * 16 * K);
        cp16(&smem[8192 + soff + p * 512], gW + (size_t)p * 16 * K);
    }
    cp_commit();

    for (int it = 0; it < kiters; ++it) {
        const int st = it & 1;
        if (it + 1 < kiters) {
            const int k0  = (it + 1) << 5;
            const int stn = (it + 1) & 1;
            #pragma unroll
            for (int p = 0; p < 8; p++) {
                cp16(&smem[stn * 4096 + soff + p * 512],        gA + k0 + (size_t)p * 16 * K);
                cp16(&smem[8192 + stn * 4096 + soff + p * 512], gW + k0 + (size_t)p * 16 * K);
            }
            cp_commit();
            cp_wait<1>();
        } else {
            cp_wait<0>();
        }
        __syncthreads();

        const uint32_t stA = smb + (uint32_t)st * 16384u + baseA;
        const uint32_t stB = smb + 32768u + (uint32_t)st * 16384u + baseB;

        #pragma unroll
        for (int kk4 = 0; kk4 < 8; kk4 += 2) {
            const uint32_t colA = (uint32_t)(((kk4 + koffA) ^ s7) << 4);
            const uint32_t colB = (uint32_t)(((kk4 + khB) ^ s7) << 4);
            // B fragments resident (16 regs)
            uint32_t bf[8][2];
            #pragma unroll
            for (int j = 0; j < 4; j++) ldsm4(&bf[2 * j][0], stB + (uint32_t)(j * 2048) + colB);
            // A fragments streamed: only 4 regs live per mf
            #pragma unroll
            for (int mf = 0; mf < 4; mf++) {
                uint32_t af[4];
                ldsm4(af, stA + (uint32_t)(mf * 2048) + colA);
                #pragma unroll
                for (int nf = 0; nf < 8; nf++)
                    mma8(acc[mf][nf], af, bf[nf]);
            }
        }
        __syncthreads();
    }

    // epilogue
    const int g = lane >> 2, t = lane & 3;
    #pragma unroll
    for (int mf = 0; mf < 4; mf++) {
        const int row = m0 + wm * 64 + mf * 16 + g;
        #pragma unroll
        for (int nf = 0; nf < 8; nf++) {
            const int col = n0 + wn * 64 + nf * 8 + 2 * t;
            const float b0 = bias[col], b1 = bias[col + 1];
            float v0 = acc[mf][nf][0] + b0;
            float v1 = acc[mf][nf][1] + b1;
            float v2 = acc[mf][nf][2] + b0;
            float v3 = acc[mf][nf][3] + b1;
            if (RELU) {
                v0 = fmaxf(v0, 0.f); v1 = fmaxf(v1, 0.f);
                v2 = fmaxf(v2, 0.f); v3 = fmaxf(v3, 0.f);
            }
            if (ROUND) {
                v0 = __uint_as_float(f2tf(v0)); v1 = __uint_as_float(f2tf(v1));
                v2 = __uint_as_float(f2tf(v2)); v3 = __uint_as_float(f2tf(v3));
            }
            *(float2*)(C + (size_t)row       * N + col) = make_float2(v0, v1);
            *(float2*)(C + (size_t)(row + 8) * N + col) = make_float2(v2, v3);
        }
    }
}

// --------------------------- tail kernels ----------------------------------
__global__ void rowops_k(const float* __restrict__ E, const float* __restrict__ XE,
                         float* __restrict__ YE,
                         const float* __restrict__ unw, const float* __restrict__ unb,
                         float* __restrict__ unpot, float* __restrict__ invnx)
{
    __shared__ float red[3][8];
    __shared__ float fin;
    const int r = blockIdx.x, tid = threadIdx.x;
    const size_t base = (size_t)r * 768;
    const int i0 = tid, i1 = tid + 256, i2 = tid + 512;
    const float e0 = E[base + i0], e1 = E[base + i1], e2 = E[base + i2];
    float de = e0 * unw[i0] + e1 * unw[i1] + e2 * unw[i2];
    const float x0 = XE[base + i0], x1 = XE[base + i1], x2 = XE[base + i2];
    float sx = x0 * x0 + x1 * x1 + x2 * x2;
    const float y0 = YE[base + i0], y1 = YE[base + i1], y2 = YE[base + i2];
    float sy = y0 * y0 + y1 * y1 + y2 * y2;
    #pragma unroll
    for (int o = 16; o; o >>= 1) {
        de += __shfl_xor_sync(0xffffffffu, de, o);
        sx += __shfl_xor_sync(0xffffffffu, sx, o);
        sy += __shfl_xor_sync(0xffffffffu, sy, o);
    }
    if ((tid & 31) == 0) { int w = tid >> 5; red[0][w] = de; red[1][w] = sx; red[2][w] = sy; }
    __syncthreads();
    if (tid == 0) {
        float a = 0.f, b2 = 0.f, c = 0.f;
        #pragma unroll
        for (int i = 0; i < 8; i++) { a += red[0][i]; b2 += red[1][i]; c += red[2][i]; }
        fin = c;
        unpot[r] = a + unb[0];
        invnx[r] = 1.f / fmaxf(sqrtf(b2), 1e-12f);
    }
    __syncthreads();
    const float inv_ny = 1.f / fmaxf(sqrtf(fin), 1e-12f);
    YE[base + i0] = y0 * inv_ny;
    YE[base + i1] = y1 * inv_ny;
    YE[base + i2] = y2 * inv_ny;
}

__global__ void ybar_k(const float* __restrict__ YN, float* __restrict__ YB)
{
    const int b = blockIdx.x, col = blockIdx.y * 128 + threadIdx.x;
    const float* p = YN + (size_t)b * 1024 * 768 + col;
    float s = 0.f;
    #pragma unroll 8
    for (int tt = 0; tt < 1024; ++tt) s += p[(size_t)tt * 768];
    YB[b * 768 + col] = s * (1.0f / 1024.0f);
}

__global__ void scores_k(const float* __restrict__ XE, const float* __restrict__ YB,
                         const float* __restrict__ invnx, const float* __restrict__ unpot,
                         const float* __restrict__ redw, float* __restrict__ sc)
{
    __shared__ float red[8];
    const int r = blockIdx.x, tid = threadIdx.x;
    const int b = r >> 10;
    const size_t base = (size_t)r * 768;
    const float* yb = YB + b * 768;
    float d = XE[base + tid] * yb[tid]
            + XE[base + tid + 256] * yb[tid + 256]
            + XE[base + tid + 512] * yb[tid + 512];
    #pragma unroll
    for (int o = 16; o; o >>= 1) d += __shfl_xor_sync(0xffffffffu, d, o);
    if ((tid & 31) == 0) red[tid >> 5] = d;
    __syncthreads();
    if (tid == 0) {
        float D = 0.f;
        #pragma unroll
        for (int i = 0; i < 8; i++) D += red[i];
        sc[r] = redw[0] * unpot[r] + redw[1] * (D * invnx[r]);
    }
}

__global__ void final_k(const float* __restrict__ U, const float* __restrict__ sc,
                        float* __restrict__ out)
{
    __shared__ float wsh[1024];
    __shared__ float red[8];
    __shared__ float finv;
    const int b = blockIdx.x, tid = threadIdx.x;
    float l0 = sc[b * 1024 + tid];
    float l1 = sc[b * 1024 + tid + 256];
    float l2 = sc[b * 1024 + tid + 512];
    float l3 = sc[b * 1024 + tid + 768];
    float mx = fmaxf(fmaxf(l0, l1), fmaxf(l2, l3));
    #pragma unroll
    for (int o = 16; o; o >>= 1) mx = fmaxf(mx, __shfl_xor_sync(0xffffffffu, mx, o));
    if ((tid & 31) == 0) red[tid >> 5] = mx;
    __syncthreads();
    if (tid == 0) {
        float M = red[0];
        #pragma unroll
        for (int i = 1; i < 8; i++) M = fmaxf(M, red[i]);
        finv = M;
    }
    __syncthreads();
    const float M = finv;
    __syncthreads();
    l0 = expf(l0 - M); l1 = expf(l1 - M); l2 = expf(l2 - M); l3 = expf(l3 - M);
    float s = l0 + l1 + l2 + l3;
    #pragma unroll
    for (int o = 16; o; o >>= 1) s += __shfl_xor_sync(0xffffffffu, s, o);
    if ((tid & 31) == 0) red[tid >> 5] = s;
    __syncthreads();
    if (tid == 0) {
        float S = 0.f;
        #pragma unroll
        for (int i = 0; i < 8; i++) S += red[i];
        finv = 1.f / S;
    }
    __syncthreads();
    const float inv = finv;
    wsh[tid]       = l0 * inv;
    wsh[tid + 256] = l1 * inv;
    wsh[tid + 512] = l2 * inv;
    wsh[tid + 768] = l3 * inv;
    __syncthreads();
    const float* Ub = U + (size_t)b * 1024 * 768;
    float a0 = 0.f, a1 = 0.f, a2 = 0.f;
    #pragma unroll 4
    for (int tt = 0; tt < 1024; ++tt) {
        const float wt = wsh[tt];
        const float* row = Ub + (size_t)tt * 768;
        a0 += wt * row[tid];
        a1 += wt * row[tid + 256];
        a2 += wt * row[tid + 512];
    }
    out[b * 768 + tid]       = a0;
    out[b * 768 + tid + 256] = a1;
    out[b * 768 + tid + 512] = a2;
}

// ---------------------------------------------------------------------------
extern "C" void kernel_launch(void* const* d_in, const int* in_sizes, int n_in,
                              void* d_out, int out_size)
{
    (void)in_sizes; (void)n_in; (void)out_size;
    const float* x        = (const float*)d_in[0];
    const float* fc1_b    = (const float*)d_in[2];
    const float* fc2_b    = (const float*)d_in[4];
    const float* un_emb_b = (const float*)d_in[6];
    const float* un_red_w = (const float*)d_in[7];
    const float* un_red_b = (const float*)d_in[8];
    const float* pw_x_b   = (const float*)d_in[10];
    const float* pw_y_b   = (const float*)d_in[12];
    const float* red_w    = (const float*)d_in[13];
    float* out = (float*)d_out;

    float *X, *H, *U, *E, *XE, *YE, *W1, *W2, *W3, *W4, *W5, *YB, *UP, *INX, *SC;
    cudaGetSymbolAddress((void**)&X,   g_X);
    cudaGetSymbolAddress((void**)&H,   g_H);
    cudaGetSymbolAddress((void**)&U,   g_U);
    cudaGetSymbolAddress((void**)&E,   g_E);
    cudaGetSymbolAddress((void**)&XE,  g_XE);
    cudaGetSymbolAddress((void**)&YE,  g_YE);
    cudaGetSymbolAddress((void**)&W1,  g_W1);
    cudaGetSymbolAddress((void**)&W2,  g_W2);
    cudaGetSymbolAddress((void**)&W3,  g_W3);
    cudaGetSymbolAddress((void**)&W4,  g_W4);
    cudaGetSymbolAddress((void**)&W5,  g_W5);
    cudaGetSymbolAddress((void**)&YB,  g_YB);
    cudaGetSymbolAddress((void**)&UP,  g_UP);
    cudaGetSymbolAddress((void**)&INX, g_INX);
    cudaGetSymbolAddress((void**)&SC,  g_SC);

    const int smem = 64 * 1024;
    cudaFuncSetAttribute((const void*)gemm_tf32<true,  true >, cudaFuncAttributeMaxDynamicSharedMemorySize, smem);
    cudaFuncSetAttribute((const void*)gemm_tf32<false, true >, cudaFuncAttributeMaxDynamicSharedMemorySize, smem);
    cudaFuncSetAttribute((const void*)gemm_tf32<true,  false>, cudaFuncAttributeMaxDynamicSharedMemorySize, smem);
    cudaFuncSetAttribute((const void*)gemm_tf32<false, false>, cudaFuncAttributeMaxDynamicSharedMemorySize, smem);

    // pre-round all GEMM operands to tf32 (rna)
    round_k<<<Mn * INn / 4 / 256, 256>>>((const float4*)x, (float4*)X, Mn * INn / 4);
    round_k<<<INn * INn / 4 / 256, 256>>>((const float4*)d_in[1], (float4*)W1, INn * INn / 4);
    round_k<<<Dn * INn / 4 / 256, 256>>>((const float4*)d_in[3], (float4*)W2, Dn * INn / 4);
    round_k<<<Dn * Dn / 4 / 256, 256>>>((const float4*)d_in[5], (float4*)W3, Dn * Dn / 4);
    round_k<<<Dn * Dn / 4 / 256, 256>>>((const float4*)d_in[9], (float4*)W4, Dn * Dn / 4);
    round_k<<<Dn * Dn / 4 / 256, 256>>>((const float4*)d_in[11], (float4*)W5, Dn * Dn / 4);

    // 1. H = round(relu(X @ W1^T + b))   [32768 x 1536], K=1536
    gemm_tf32<true, true><<<dim3(12, 256), 128, smem>>>(X, W1, fc1_b, H, 1536, 1536);
    // 2. U = round(H @ W2^T + b)         [32768 x 768], K=1536
    gemm_tf32<false, true><<<dim3(6, 256), 128, smem>>>(H, W2, fc2_b, U, 768, 1536);
    // 3-5. E / XE / YE                   [32768 x 768], K=768
    gemm_tf32<true, false><<<dim3(6, 256), 128, smem>>>(U, W3, un_emb_b, E, 768, 768);
    gemm_tf32<false, false><<<dim3(6, 256), 128, smem>>>(U, W4, pw_x_b, XE, 768, 768);
    gemm_tf32<false, false><<<dim3(6, 256), 128, smem>>>(U, W5, pw_y_b, YE, 768, 768);
    // 6-9. reductions, scores, softmax-weighted sum
    rowops_k<<<Mn, 256>>>(E, XE, YE, un_red_w, un_red_b, UP, INX);
    ybar_k<<<dim3(Bn, 6), 128>>>(YE, YB);
    scores_k<<<Mn, 256>>>(XE, YB, INX, UP, red_w, SC);
    final_k<<<Bn, 256>>>(U, SC, out);
}

// round 10
// speedup vs baseline: 1.4823x; 1.4823x over previous
#include <cuda_runtime.h>
#include <cstdint>
#include <cstddef>

namespace {
constexpr int Bn = 32, Tn = 1024, INn = 1536, Dn = 768;
constexpr int Mn = Bn * Tn;  // 32768
constexpr int GSMEM = 96 * 1024;  // 3 stages x (A 16KB + B 16KB)
}

// Scratch (static __device__ globals: allocation-free rule)
__device__ __align__(256) float g_X [(size_t)Mn * INn];
__device__ __align__(256) float g_H [(size_t)Mn * INn];
__device__ __align__(256) float g_U [(size_t)Mn * Dn];
__device__ __align__(256) float g_E [(size_t)Mn * Dn];
__device__ __align__(256) float g_XE[(size_t)Mn * Dn];
__device__ __align__(256) float g_YE[(size_t)Mn * Dn];
__device__ __align__(256) float g_W1[(size_t)INn * INn];
__device__ __align__(256) float g_W2[(size_t)Dn * INn];
__device__ __align__(256) float g_W3[(size_t)Dn * Dn];
__device__ __align__(256) float g_W4[(size_t)Dn * Dn];
__device__ __align__(256) float g_W5[(size_t)Dn * Dn];
__device__ __align__(256) float g_YB[Bn * Dn];
__device__ __align__(256) float g_UP[Mn];
__device__ __align__(256) float g_INX[Mn];
__device__ __align__(256) float g_SC[Mn];

// ---------------------------------------------------------------------------
// helpers
// ---------------------------------------------------------------------------
__device__ __forceinline__ uint32_t smem_u32(const void* p) {
    uint32_t a;
    asm("{ .reg .u64 t; cvta.to.shared.u64 t, %1; cvt.u32.u64 %0, t; }" : "=r"(a) : "l"(p));
    return a;
}
__device__ __forceinline__ void cp16(float* s, const float* g) {
    uint32_t sa = (uint32_t)__cvta_generic_to_shared(s);
    asm volatile("cp.async.cg.shared.global [%0], [%1], 16;\n" :: "r"(sa), "l"(g));
}
__device__ __forceinline__ void cp_commit() { asm volatile("cp.async.commit_group;\n"); }
template <int NW> __device__ __forceinline__ void cp_wait() {
    asm volatile("cp.async.wait_group %0;\n" :: "n"(NW));
}
__device__ __forceinline__ uint32_t f2tf(float x) {
    uint32_t r;
    asm("cvt.rna.tf32.f32 %0, %1;\n" : "=r"(r) : "f"(x));
    return r;
}
__device__ __forceinline__ void mma8(float* c, const uint32_t* a, const uint32_t* b) {
    asm volatile(
        "mma.sync.aligned.m16n8k8.row.col.f32.tf32.tf32.f32 "
        "{%0,%1,%2,%3}, {%4,%5,%6,%7}, {%8,%9}, {%0,%1,%2,%3};\n"
        : "+f"(c[0]), "+f"(c[1]), "+f"(c[2]), "+f"(c[3])
        : "r"(a[0]), "r"(a[1]), "r"(a[2]), "r"(a[3]), "r"(b[0]), "r"(b[1]));
}
__device__ __forceinline__ void ldsm4(uint32_t* r, uint32_t addr) {
    asm volatile("ldmatrix.sync.aligned.m8n8.x4.shared.b16 {%0,%1,%2,%3}, [%4];"
                 : "=r"(r[0]), "=r"(r[1]), "=r"(r[2]), "=r"(r[3]) : "r"(addr));
}
__device__ __forceinline__ void ldsm2(uint32_t* r, uint32_t addr) {
    asm volatile("ldmatrix.sync.aligned.m8n8.x2.shared.b16 {%0,%1}, [%2];"
                 : "=r"(r[0]), "=r"(r[1]) : "r"(addr));
}

__global__ void round_k(const float4* __restrict__ src, float4* __restrict__ dst, int n4)
{
    int i = blockIdx.x * 256 + threadIdx.x;
    if (i >= n4) return;
    float4 v = src[i];
    v.x = __uint_as_float(f2tf(v.x)); v.y = __uint_as_float(f2tf(v.y));
    v.z = __uint_as_float(f2tf(v.z)); v.w = __uint_as_float(f2tf(v.w));
    dst[i] = v;
}
// batched rounding of the 5 weight matrices in one launch
struct RoundBatch { const float4* s[5]; float4* d[5]; int n4[5]; int off[6]; };
__global__ void round_batch_k(RoundBatch rb)
{
    int i = blockIdx.x * 256 + threadIdx.x;
    #pragma unroll
    for (int j = 0; j < 5; j++) {
        if (i >= rb.off[j] && i < rb.off[j + 1]) {
            int k = i - rb.off[j];
            float4 v = rb.s[j][k];
            v.x = __uint_as_float(f2tf(v.x)); v.y = __uint_as_float(f2tf(v.y));
            v.z = __uint_as_float(f2tf(v.z)); v.w = __uint_as_float(f2tf(v.w));
            rb.d[j][k] = v;
        }
    }
}

// ---------------------------------------------------------------------------
// GEMM: C[M,N] = A[M,K] @ W[N,K]^T + bias[N], optional relu / output rounding.
// Inputs tf32-valued. CTA 128x128x32, 256 threads, 8 warps 2(m)x4(n), warp
// tile 64x32 (R5 geometry), m16n8k8 tf32 via ldmatrix, 3-stage cp.async
// single-sync pipeline, 2 CTAs/SM. M%128==0, N%128==0, K%32==0, K/32>=2.
// SMEM floats: A stage s at s*4096 (16KB), B stage s at 12288+s*4096 (16KB).
// ---------------------------------------------------------------------------
template <bool RELU, bool ROUND>
__global__ __launch_bounds__(256, 2) void gemm_tf32(
    const float* __restrict__ A, const float* __restrict__ W,
    const float* __restrict__ bias, float* __restrict__ C,
    int N, int K)
{
    extern __shared__ float smem[];
    const int tid  = threadIdx.x;
    const int lane = tid & 31, wrp = tid >> 5;
    const int wm = wrp >> 2, wn = wrp & 3;          // 2 x 4 warp grid
    const int m0 = blockIdx.y * 128, n0 = blockIdx.x * 128;

    // loader: thread -> col-group c4 (0..7), base row rb (0..31), rows rb+32p
    const int c4 = tid & 7, rb = tid >> 3;
    const int soff = rb * 32 + ((c4 ^ (rb & 7)) << 2);   // (rb+32p)&7 == rb&7
    const float* gA = A + (size_t)(m0 + rb) * K + c4 * 4;
    const float* gW = W + (size_t)(n0 + rb) * K + c4 * 4;

    auto load_stage = [&](int s, int k0) {
        float* sA = smem + s * 4096;
        float* sB = smem + 12288 + s * 4096;
        #pragma unroll
        for (int p = 0; p < 4; p++) cp16(&sA[soff + p * 1024], gA + k0 + (size_t)p * 32 * K);
        #pragma unroll
        for (int p = 0; p < 4; p++) cp16(&sB[soff + p * 1024], gW + k0 + (size_t)p * 32 * K);
        cp_commit();
    };

    // ldmatrix per-lane geometry (R5)
    const uint32_t smb = smem_u32(smem);
    const int s7 = lane & 7;
    const int half  = (lane >> 3) & 1;   // A: +8 rows for matrices 1,3
    const int koffA = lane >> 4;         // A: +1 col4 for matrices 2,3
    const int koffB = (lane >> 3) & 1;   // B: +1 col4 for matrix 1
    uint32_t rowA[4], rowB[4];
    #pragma unroll
    for (int mf = 0; mf < 4; mf++)
        rowA[mf] = (uint32_t)(wm * 64 + mf * 16 + half * 8 + s7) * 128u;
    #pragma unroll
    for (int nf = 0; nf < 4; nf++)
        rowB[nf] = (uint32_t)(wn * 32 + nf * 8 + s7) * 128u;

    float acc[4][4][4];
    #pragma unroll
    for (int i = 0; i < 4; i++)
        #pragma unroll
        for (int j = 0; j < 4; j++)
            #pragma unroll
            for (int q = 0; q < 4; q++) acc[i][j][q] = 0.f;

    const int kiters = K >> 5;
    load_stage(0, 0);
    load_stage(1, 32);

    for (int it = 0; it < kiters; ++it) {
        if (it == kiters - 1) cp_wait<0>(); else cp_wait<1>();
        __syncthreads();
        if (it + 2 < kiters) load_stage((it + 2) % 3, (it + 2) << 5);

        const int st = it % 3;
        const uint32_t stA = smb + (uint32_t)st * 16384u;
        const uint32_t stB = smb + 49152u + (uint32_t)st * 16384u;

        #pragma unroll
        for (int kk4 = 0; kk4 < 8; kk4 += 2) {
            const uint32_t colA = (uint32_t)(((kk4 + koffA) ^ s7) << 4);
            const uint32_t colB = (uint32_t)(((kk4 + koffB) ^ s7) << 4);
            uint32_t af[4][4], bf[4][2];
            #pragma unroll
            for (int mf = 0; mf < 4; mf++) ldsm4(af[mf], stA + rowA[mf] + colA);
            #pragma unroll
            for (int nf = 0; nf < 4; nf++) ldsm2(bf[nf], stB + rowB[nf] + colB);
            #pragma unroll
            for (int mf = 0; mf < 4; mf++)
                #pragma unroll
                for (int nf = 0; nf < 4; nf++)
                    mma8(acc[mf][nf], af[mf], bf[nf]);
        }
    }

    // epilogue: bias (+relu), optional tf32-round, float2 stores
    const int g = lane >> 2, t = lane & 3;
    #pragma unroll
    for (int mf = 0; mf < 4; mf++) {
        const int row = m0 + wm * 64 + mf * 16 + g;
        #pragma unroll
        for (int nf = 0; nf < 4; nf++) {
            const int col = n0 + wn * 32 + nf * 8 + 2 * t;
            const float b0 = bias[col], b1 = bias[col + 1];
            float v0 = acc[mf][nf][0] + b0;
            float v1 = acc[mf][nf][1] + b1;
            float v2 = acc[mf][nf][2] + b0;
            float v3 = acc[mf][nf][3] + b1;
            if (RELU) {
                v0 = fmaxf(v0, 0.f); v1 = fmaxf(v1, 0.f);
                v2 = fmaxf(v2, 0.f); v3 = fmaxf(v3, 0.f);
            }
            if (ROUND) {
                v0 = __uint_as_float(f2tf(v0)); v1 = __uint_as_float(f2tf(v1));
                v2 = __uint_as_float(f2tf(v2)); v3 = __uint_as_float(f2tf(v3));
            }
            *(float2*)(C + (size_t)row       * N + col) = make_float2(v0, v1);
            *(float2*)(C + (size_t)(row + 8) * N + col) = make_float2(v2, v3);
        }
    }
}

// --------------------------- tail kernels ----------------------------------
__global__ void rowops_k(const float* __restrict__ E, const float* __restrict__ XE,
                         float* __restrict__ YE,
                         const float* __restrict__ unw, const float* __restrict__ unb,
                         float* __restrict__ unpot, float* __restrict__ invnx)
{
    __shared__ float red[3][8];
    __shared__ float fin;
    const int r = blockIdx.x, tid = threadIdx.x;
    const size_t base = (size_t)r * 768;
    const int i0 = tid, i1 = tid + 256, i2 = tid + 512;
    const float e0 = E[base + i0], e1 = E[base + i1], e2 = E[base + i2];
    float de = e0 * unw[i0] + e1 * unw[i1] + e2 * unw[i2];
    const float x0 = XE[base + i0], x1 = XE[base + i1], x2 = XE[base + i2];
    float sx = x0 * x0 + x1 * x1 + x2 * x2;
    const float y0 = YE[base + i0], y1 = YE[base + i1], y2 = YE[base + i2];
    float sy = y0 * y0 + y1 * y1 + y2 * y2;
    #pragma unroll
    for (int o = 16; o; o >>= 1) {
        de += __shfl_xor_sync(0xffffffffu, de, o);
        sx += __shfl_xor_sync(0xffffffffu, sx, o);
        sy += __shfl_xor_sync(0xffffffffu, sy, o);
    }
    if ((tid & 31) == 0) { int w = tid >> 5; red[0][w] = de; red[1][w] = sx; red[2][w] = sy; }
    __syncthreads();
    if (tid == 0) {
        float a = 0.f, b2 = 0.f, c = 0.f;
        #pragma unroll
        for (int i = 0; i < 8; i++) { a += red[0][i]; b2 += red[1][i]; c += red[2][i]; }
        fin = c;
        unpot[r] = a + unb[0];
        invnx[r] = 1.f / fmaxf(sqrtf(b2), 1e-12f);
    }
    __syncthreads();
    const float inv_ny = 1.f / fmaxf(sqrtf(fin), 1e-12f);
    YE[base + i0] = y0 * inv_ny;
    YE[base + i1] = y1 * inv_ny;
    YE[base + i2] = y2 * inv_ny;
}

__global__ void ybar_k(const float* __restrict__ YN, float* __restrict__ YB)
{
    const int b = blockIdx.x, col = blockIdx.y * 128 + threadIdx.x;
    const float* p = YN + (size_t)b * 1024 * 768 + col;
    float s = 0.f;
    #pragma unroll 8
    for (int tt = 0; tt < 1024; ++tt) s += p[(size_t)tt * 768];
    YB[b * 768 + col] = s * (1.0f / 1024.0f);
}

__global__ void scores_k(const float* __restrict__ XE, const float* __restrict__ YB,
                         const float* __restrict__ invnx, const float* __restrict__ unpot,
                         const float* __restrict__ redw, float* __restrict__ sc)
{
    __shared__ float red[8];
    const int r = blockIdx.x, tid = threadIdx.x;
    const int b = r >> 10;
    const size_t base = (size_t)r * 768;
    const float* yb = YB + b * 768;
    float d = XE[base + tid] * yb[tid]
            + XE[base + tid + 256] * yb[tid + 256]
            + XE[base + tid + 512] * yb[tid + 512];
    #pragma unroll
    for (int o = 16; o; o >>= 1) d += __shfl_xor_sync(0xffffffffu, d, o);
    if ((tid & 31) == 0) red[tid >> 5] = d;
    __syncthreads();
    if (tid == 0) {
        float D = 0.f;
        #pragma unroll
        for (int i = 0; i < 8; i++) D += red[i];
        sc[r] = redw[0] * unpot[r] + redw[1] * (D * invnx[r]);
    }
}

__global__ void final_k(const float* __restrict__ U, const float* __restrict__ sc,
                        float* __restrict__ out)
{
    __shared__ float wsh[1024];
    __shared__ float red[8];
    __shared__ float finv;
    const int b = blockIdx.x, tid = threadIdx.x;
    float l0 = sc[b * 1024 + tid];
    float l1 = sc[b * 1024 + tid + 256];
    float l2 = sc[b * 1024 + tid + 512];
    float l3 = sc[b * 1024 + tid + 768];
    float mx = fmaxf(fmaxf(l0, l1), fmaxf(l2, l3));
    #pragma unroll
    for (int o = 16; o; o >>= 1) mx = fmaxf(mx, __shfl_xor_sync(0xffffffffu, mx, o));
    if ((tid & 31) == 0) red[tid >> 5] = mx;
    __syncthreads();
    if (tid == 0) {
        float M = red[0];
        #pragma unroll
        for (int i = 1; i < 8; i++) M = fmaxf(M, red[i]);
        finv = M;
    }
    __syncthreads();
    const float M = finv;
    __syncthreads();
    l0 = expf(l0 - M); l1 = expf(l1 - M); l2 = expf(l2 - M); l3 = expf(l3 - M);
    float s = l0 + l1 + l2 + l3;
    #pragma unroll
    for (int o = 16; o; o >>= 1) s += __shfl_xor_sync(0xffffffffu, s, o);
    if ((tid & 31) == 0) red[tid >> 5] = s;
    __syncthreads();
    if (tid == 0) {
        float S = 0.f;
        #pragma unroll
        for (int i = 0; i < 8; i++) S += red[i];
        finv = 1.f / S;
    }
    __syncthreads();
    const float inv = finv;
    wsh[tid]       = l0 * inv;
    wsh[tid + 256] = l1 * inv;
    wsh[tid + 512] = l2 * inv;
    wsh[tid + 768] = l3 * inv;
    __syncthreads();
    const float* Ub = U + (size_t)b * 1024 * 768;
    float a0 = 0.f, a1 = 0.f, a2 = 0.f;
    #pragma unroll 4
    for (int tt = 0; tt < 1024; ++tt) {
        const float wt = wsh[tt];
        const float* row = Ub + (size_t)tt * 768;
        a0 += wt * row[tid];
        a1 += wt * row[tid + 256];
        a2 += wt * row[tid + 512];
    }
    out[b * 768 + tid]       = a0;
    out[b * 768 + tid + 256] = a1;
    out[b * 768 + tid + 512] = a2;
}

// ---------------------------------------------------------------------------
extern "C" void kernel_launch(void* const* d_in, const int* in_sizes, int n_in,
                              void* d_out, int out_size)
{
    (void)in_sizes; (void)n_in; (void)out_size;
    const float* x        = (const float*)d_in[0];
    const float* fc1_b    = (const float*)d_in[2];
    const float* fc2_b    = (const float*)d_in[4];
    const float* un_emb_b = (const float*)d_in[6];
    const float* un_red_w = (const float*)d_in[7];
    const float* un_red_b = (const float*)d_in[8];
    const float* pw_x_b   = (const float*)d_in[10];
    const float* pw_y_b   = (const float*)d_in[12];
    const float* red_w    = (const float*)d_in[13];
    float* out = (float*)d_out;

    float *X, *H, *U, *E, *XE, *YE, *W1, *W2, *W3, *W4, *W5, *YB, *UP, *INX, *SC;
    cudaGetSymbolAddress((void**)&X,   g_X);
    cudaGetSymbolAddress((void**)&H,   g_H);
    cudaGetSymbolAddress((void**)&U,   g_U);
    cudaGetSymbolAddress((void**)&E,   g_E);
    cudaGetSymbolAddress((void**)&XE,  g_XE);
    cudaGetSymbolAddress((void**)&YE,  g_YE);
    cudaGetSymbolAddress((void**)&W1,  g_W1);
    cudaGetSymbolAddress((void**)&W2,  g_W2);
    cudaGetSymbolAddress((void**)&W3,  g_W3);
    cudaGetSymbolAddress((void**)&W4,  g_W4);
    cudaGetSymbolAddress((void**)&W5,  g_W5);
    cudaGetSymbolAddress((void**)&YB,  g_YB);
    cudaGetSymbolAddress((void**)&UP,  g_UP);
    cudaGetSymbolAddress((void**)&INX, g_INX);
    cudaGetSymbolAddress((void**)&SC,  g_SC);

    cudaFuncSetAttribute((const void*)gemm_tf32<true,  true >, cudaFuncAttributeMaxDynamicSharedMemorySize, GSMEM);
    cudaFuncSetAttribute((const void*)gemm_tf32<false, true >, cudaFuncAttributeMaxDynamicSharedMemorySize, GSMEM);
    cudaFuncSetAttribute((const void*)gemm_tf32<true,  false>, cudaFuncAttributeMaxDynamicSharedMemorySize, GSMEM);
    cudaFuncSetAttribute((const void*)gemm_tf32<false, false>, cudaFuncAttributeMaxDynamicSharedMemorySize, GSMEM);

    // pre-round x (big, own launch) + the 5 weight matrices (one batched launch)
    round_k<<<Mn * INn / 4 / 256, 256>>>((const float4*)x, (float4*)X, Mn * INn / 4);
    {
        RoundBatch rb;
        const int n1 = INn * INn / 4, n2 = Dn * INn / 4, n3 = Dn * Dn / 4;
        rb.s[0] = (const float4*)d_in[1];  rb.d[0] = (float4*)W1; rb.n4[0] = n1;
        rb.s[1] = (const float4*)d_in[3];  rb.d[1] = (float4*)W2; rb.n4[1] = n2;
        rb.s[2] = (const float4*)d_in[5];  rb.d[2] = (float4*)W3; rb.n4[2] = n3;
        rb.s[3] = (const float4*)d_in[9];  rb.d[3] = (float4*)W4; rb.n4[3] = n3;
        rb.s[4] = (const float4*)d_in[11]; rb.d[4] = (float4*)W5; rb.n4[4] = n3;
        rb.off[0] = 0;
        for (int j = 0; j < 5; j++) rb.off[j + 1] = rb.off[j] + rb.n4[j];
        round_batch_k<<<(rb.off[5] + 255) / 256, 256>>>(rb);
    }

    // 1. H = round(relu(X @ W1^T + b))   [32768 x 1536], K=1536
    gemm_tf32<true, true><<<dim3(12, 256), 256, GSMEM>>>(X, W1, fc1_b, H, 1536, 1536);
    // 2. U = round(H @ W2^T + b)         [32768 x 768], K=1536
    gemm_tf32<false, true><<<dim3(6, 256), 256, GSMEM>>>(H, W2, fc2_b, U, 768, 1536);
    // 3-5. E / XE / YE                   [32768 x 768], K=768
    gemm_tf32<true, false><<<dim3(6, 256), 256, GSMEM>>>(U, W3, un_emb_b, E, 768, 768);
    gemm_tf32<false, false><<<dim3(6, 256), 256, GSMEM>>>(U, W4, pw_x_b, XE, 768, 768);
    gemm_tf32<false, false><<<dim3(6, 256), 256, GSMEM>>>(U, W5, pw_y_b, YE, 768, 768);
    // 6-9. reductions, scores, softmax-weighted sum
    rowops_k<<<Mn, 256>>>(E, XE, YE, un_red_w, un_red_b, UP, INX);
    ybar_k<<<dim3(Bn, 6), 128>>>(YE, YB);
    scores_k<<<Mn, 256>>>(XE, YB, INX, UP, red_w, SC);
    final_k<<<Bn, 256>>>(U, SC, out);
}

// round 11
// speedup vs baseline: 1.5590x; 1.0517x over previous
#include <cuda_runtime.h>
#include <cstdint>
#include <cstddef>

namespace {
constexpr int Bn = 32, Tn = 1024, INn = 1536, Dn = 768;
constexpr int Mn = Bn * Tn;  // 32768
constexpr int GSMEM = 96 * 1024;  // 3 stages x (A 16KB + B 16KB)
}

// Scratch (static __device__ globals: allocation-free rule)
__device__ __align__(256) float g_X [(size_t)Mn * INn];
__device__ __align__(256) float g_H [(size_t)Mn * INn];
__device__ __align__(256) float g_U [(size_t)Mn * Dn];
__device__ __align__(256) float g_XE[(size_t)Mn * Dn];
__device__ __align__(256) float g_YE[(size_t)Mn * Dn];
__device__ __align__(256) float g_W1[(size_t)INn * INn];
__device__ __align__(256) float g_W2[(size_t)Dn * INn];
__device__ __align__(256) float g_Wc[(size_t)3 * Dn * Dn];   // [2304 x 768] concat W3|W4|W5
__device__ __align__(256) float g_PT[(size_t)18 * Mn];       // per-(nblock,row) partials
__device__ __align__(256) float g_YB[Bn * Dn];
__device__ __align__(256) float g_UP[Mn];
__device__ __align__(256) float g_INX[Mn];
__device__ __align__(256) float g_INY[Mn];
__device__ __align__(256) float g_SC[Mn];

// ---------------------------------------------------------------------------
// helpers
// ---------------------------------------------------------------------------
__device__ __forceinline__ uint32_t smem_u32(const void* p) {
    uint32_t a;
    asm("{ .reg .u64 t; cvta.to.shared.u64 t, %1; cvt.u32.u64 %0, t; }" : "=r"(a) : "l"(p));
    return a;
}
__device__ __forceinline__ void cp16(float* s, const float* g) {
    uint32_t sa = (uint32_t)__cvta_generic_to_shared(s);
    asm volatile("cp.async.cg.shared.global [%0], [%1], 16;\n" :: "r"(sa), "l"(g));
}
__device__ __forceinline__ void cp_commit() { asm volatile("cp.async.commit_group;\n"); }
template <int NW> __device__ __forceinline__ void cp_wait() {
    asm volatile("cp.async.wait_group %0;\n" :: "n"(NW));
}
__device__ __forceinline__ uint32_t f2tf(float x) {
    uint32_t r;
    asm("cvt.rna.tf32.f32 %0, %1;\n" : "=r"(r) : "f"(x));
    return r;
}
__device__ __forceinline__ void mma8(float* c, const uint32_t* a, const uint32_t* b) {
    asm volatile(
        "mma.sync.aligned.m16n8k8.row.col.f32.tf32.tf32.f32 "
        "{%0,%1,%2,%3}, {%4,%5,%6,%7}, {%8,%9}, {%0,%1,%2,%3};\n"
        : "+f"(c[0]), "+f"(c[1]), "+f"(c[2]), "+f"(c[3])
        : "r"(a[0]), "r"(a[1]), "r"(a[2]), "r"(a[3]), "r"(b[0]), "r"(b[1]));
}
__device__ __forceinline__ void ldsm4(uint32_t* r, uint32_t addr) {
    asm volatile("ldmatrix.sync.aligned.m8n8.x4.shared.b16 {%0,%1,%2,%3}, [%4];"
                 : "=r"(r[0]), "=r"(r[1]), "=r"(r[2]), "=r"(r[3]) : "r"(addr));
}
__device__ __forceinline__ void ldsm2(uint32_t* r, uint32_t addr) {
    asm volatile("ldmatrix.sync.aligned.m8n8.x2.shared.b16 {%0,%1}, [%2];"
                 : "=r"(r[0]), "=r"(r[1]) : "r"(addr));
}

__global__ void round_k(const float4* __restrict__ src, float4* __restrict__ dst, int n4)
{
    int i = blockIdx.x * 256 + threadIdx.x;
    if (i >= n4) return;
    float4 v = src[i];
    v.x = __uint_as_float(f2tf(v.x)); v.y = __uint_as_float(f2tf(v.y));
    v.z = __uint_as_float(f2tf(v.z)); v.w = __uint_as_float(f2tf(v.w));
    dst[i] = v;
}
struct RoundBatch { const float4* s[5]; float4* d[5]; int off[6]; };
__global__ void round_batch_k(RoundBatch rb)
{
    int i = blockIdx.x * 256 + threadIdx.x;
    #pragma unroll
    for (int j = 0; j < 5; j++) {
        if (i >= rb.off[j] && i < rb.off[j + 1]) {
            int k = i - rb.off[j];
            float4 v = rb.s[j][k];
            v.x = __uint_as_float(f2tf(v.x)); v.y = __uint_as_float(f2tf(v.y));
            v.z = __uint_as_float(f2tf(v.z)); v.w = __uint_as_float(f2tf(v.w));
            rb.d[j][k] = v;
        }
    }
}

// ---------------------------------------------------------------------------
// Shared GEMM mainloop macro-structure (R5/R10 proven geometry):
// CTA 128x128x32, 256 threads, 8 warps 2(m)x4(n), warp tile 64x32,
// 3-stage cp.async single-sync pipeline, 2 CTAs/SM.
// ---------------------------------------------------------------------------
#define GEMM_PREAMBLE_AND_MAINLOOP(APTR, WPTR, KVAL)                                    \
    extern __shared__ float smem[];                                                     \
    const int tid  = threadIdx.x;                                                       \
    const int lane = tid & 31, wrp = tid >> 5;                                          \
    const int wm = wrp >> 2, wn = wrp & 3;                                              \
    const int m0 = blockIdx.y * 128, n0 = blockIdx.x * 128;                             \
    const int c4 = tid & 7, rb = tid >> 3;                                              \
    const int soff = rb * 32 + ((c4 ^ (rb & 7)) << 2);                                  \
    const float* gA = (APTR) + (size_t)(m0 + rb) * (KVAL) + c4 * 4;                     \
    const float* gW = (WPTR) + (size_t)(n0 + rb) * (KVAL) + c4 * 4;                     \
    auto load_stage = [&](int s, int k0) {                                              \
        float* sA = smem + s * 4096;                                                    \
        float* sB = smem + 12288 + s * 4096;                                            \
        _Pragma("unroll")                                                               \
        for (int p = 0; p < 4; p++) cp16(&sA[soff + p * 1024], gA + k0 + (size_t)p * 32 * (KVAL)); \
        _Pragma("unroll")                                                               \
        for (int p = 0; p < 4; p++) cp16(&sB[soff + p * 1024], gW + k0 + (size_t)p * 32 * (KVAL)); \
        cp_commit();                                                                    \
    };                                                                                  \
    const uint32_t smb = smem_u32(smem);                                                \
    const int s7 = lane & 7;                                                            \
    const int half  = (lane >> 3) & 1;                                                  \
    const int koffA = lane >> 4;                                                        \
    const int koffB = (lane >> 3) & 1;                                                  \
    uint32_t rowA[4], rowB[4];                                                          \
    _Pragma("unroll")                                                                   \
    for (int mf = 0; mf < 4; mf++)                                                      \
        rowA[mf] = (uint32_t)(wm * 64 + mf * 16 + half * 8 + s7) * 128u;                \
    _Pragma("unroll")                                                                   \
    for (int nf = 0; nf < 4; nf++)                                                      \
        rowB[nf] = (uint32_t)(wn * 32 + nf * 8 + s7) * 128u;                            \
    float acc[4][4][4];                                                                 \
    _Pragma("unroll")                                                                   \
    for (int i = 0; i < 4; i++)                                                         \
        _Pragma("unroll")                                                               \
        for (int j = 0; j < 4; j++)                                                     \
            _Pragma("unroll")                                                           \
            for (int q = 0; q < 4; q++) acc[i][j][q] = 0.f;                             \
    const int kiters = (KVAL) >> 5;                                                     \
    load_stage(0, 0);                                                                   \
    load_stage(1, 32);                                                                  \
    for (int it = 0; it < kiters; ++it) {                                               \
        if (it == kiters - 1) cp_wait<0>(); else cp_wait<1>();                          \
        __syncthreads();                                                                \
        if (it + 2 < kiters) load_stage((it + 2) % 3, (it + 2) << 5);                   \
        const int st = it % 3;                                                          \
        const uint32_t stA = smb + (uint32_t)st * 16384u;                               \
        const uint32_t stB = smb + 49152u + (uint32_t)st * 16384u;                      \
        _Pragma("unroll")                                                               \
        for (int kk4 = 0; kk4 < 8; kk4 += 2) {                                          \
            const uint32_t colA = (uint32_t)(((kk4 + koffA) ^ s7) << 4);                \
            const uint32_t colB = (uint32_t)(((kk4 + koffB) ^ s7) << 4);                \
            uint32_t af[4][4], bf[4][2];                                                \
            _Pragma("unroll")                                                           \
            for (int mf = 0; mf < 4; mf++) ldsm4(af[mf], stA + rowA[mf] + colA);        \
            _Pragma("unroll")                                                           \
            for (int nf = 0; nf < 4; nf++) ldsm2(bf[nf], stB + rowB[nf] + colB);        \
            _Pragma("unroll")                                                           \
            for (int mf = 0; mf < 4; mf++)                                              \
                _Pragma("unroll")                                                       \
                for (int nf = 0; nf < 4; nf++)                                          \
                    mma8(acc[mf][nf], af[mf], bf[nf]);                                  \
        }                                                                               \
    }

// Plain GEMM: C = A@W^T + bias, optional relu / tf32-round of outputs (fc1/fc2)
template <bool RELU, bool ROUND>
__global__ __launch_bounds__(256, 2) void gemm_tf32(
    const float* __restrict__ A, const float* __restrict__ W,
    const float* __restrict__ bias, float* __restrict__ C,
    int N, int K)
{
    GEMM_PREAMBLE_AND_MAINLOOP(A, W, K)

    const int g = lane >> 2, t = lane & 3;
    #pragma unroll
    for (int mf = 0; mf < 4; mf++) {
        const int row = m0 + wm * 64 + mf * 16 + g;
        #pragma unroll
        for (int nf = 0; nf < 4; nf++) {
            const int col = n0 + wn * 32 + nf * 8 + 2 * t;
            const float b0 = bias[col], b1 = bias[col + 1];
            float v0 = acc[mf][nf][0] + b0;
            float v1 = acc[mf][nf][1] + b1;
            float v2 = acc[mf][nf][2] + b0;
            float v3 = acc[mf][nf][3] + b1;
            if (RELU) {
                v0 = fmaxf(v0, 0.f); v1 = fmaxf(v1, 0.f);
                v2 = fmaxf(v2, 0.f); v3 = fmaxf(v3, 0.f);
            }
            if (ROUND) {
                v0 = __uint_as_float(f2tf(v0)); v1 = __uint_as_float(f2tf(v1));
                v2 = __uint_as_float(f2tf(v2)); v3 = __uint_as_float(f2tf(v3));
            }
            *(float2*)(C + (size_t)row       * N + col) = make_float2(v0, v1);
            *(float2*)(C + (size_t)(row + 8) * N + col) = make_float2(v2, v3);
        }
    }
}

// Fused D-GEMM: N=2304 concat [E | XE | YE] against Wc.
// seg 0 (cols 0-767):    E = relu(.+b_e); reduce E·unred per row -> partials, no store
// seg 1 (cols 768-1535): XE = .+b_x; store; reduce x^2 per row -> partials
// seg 2 (cols 1536+):    YE = .+b_y; store; reduce y^2 per row -> partials
// Deterministic smem tree: part2[128][17], then 16-way sum -> g_PT[nb*Mn + row].
__global__ __launch_bounds__(256, 2) void gemm_fused3(
    const float* __restrict__ A, const float* __restrict__ W,
    const float* __restrict__ b_e, const float* __restrict__ b_x,
    const float* __restrict__ b_y, const float* __restrict__ unred,
    float* __restrict__ XE, float* __restrict__ YE, float* __restrict__ PT)
{
    GEMM_PREAMBLE_AND_MAINLOOP(A, W, 768)

    const int g = lane >> 2, t = lane & 3;
    const int seg = blockIdx.x / 6;              // 0:E 1:XE 2:YE
    const float* bias = (seg == 0) ? b_e : (seg == 1) ? b_x : b_y;
    float* Cseg = (seg == 1) ? XE : YE;
    const int cb0 = (blockIdx.x - seg * 6) * 128 + wn * 32;  // segment-local col base

    __syncthreads();                     // stages dead; reuse smem for part2[128][17]
    float* part2 = smem;

    #pragma unroll
    for (int mf = 0; mf < 4; mf++) {
        const int row = wm * 64 + mf * 16 + g;   // CTA-local row
        float ps0 = 0.f, ps1 = 0.f;
        #pragma unroll
        for (int nf = 0; nf < 4; nf++) {
            const int cs = cb0 + nf * 8 + 2 * t;
            const float b0 = bias[cs], b1 = bias[cs + 1];
            float v0 = acc[mf][nf][0] + b0;
            float v1 = acc[mf][nf][1] + b1;
            float v2 = acc[mf][nf][2] + b0;
            float v3 = acc[mf][nf][3] + b1;
            if (seg == 0) {
                v0 = fmaxf(v0, 0.f); v1 = fmaxf(v1, 0.f);
                v2 = fmaxf(v2, 0.f); v3 = fmaxf(v3, 0.f);
                const float w0 = unred[cs], w1 = unred[cs + 1];
                ps0 += v0 * w0 + v1 * w1;
                ps1 += v2 * w0 + v3 * w1;
            } else {
                ps0 += v0 * v0 + v1 * v1;
                ps1 += v2 * v2 + v3 * v3;
                *(float2*)(Cseg + (size_t)(m0 + row)     * 768 + cs) = make_float2(v0, v1);
                *(float2*)(Cseg + (size_t)(m0 + row + 8) * 768 + cs) = make_float2(v2, v3);
            }
        }
        part2[row * 17 + wn * 4 + t]       = ps0;
        part2[(row + 8) * 17 + wn * 4 + t] = ps1;
    }
    __syncthreads();
    if (tid < 128) {
        float s = 0.f;
        #pragma unroll
        for (int c = 0; c < 16; c++) s += part2[tid * 17 + c];
        PT[(size_t)blockIdx.x * Mn + m0 + tid] = s;
    }
}

// --------------------------- tail kernels ----------------------------------
__global__ void combine_k(const float* __restrict__ PT, const float* __restrict__ unb,
                          float* __restrict__ up, float* __restrict__ inx,
                          float* __restrict__ iny)
{
    const int r = blockIdx.x * 256 + threadIdx.x;
    float a = 0.f, b = 0.f, c = 0.f;
    #pragma unroll
    for (int nb = 0; nb < 6; nb++)  a += PT[(size_t)nb * Mn + r];
    #pragma unroll
    for (int nb = 6; nb < 12; nb++) b += PT[(size_t)nb * Mn + r];
    #pragma unroll
    for (int nb = 12; nb < 18; nb++) c += PT[(size_t)nb * Mn + r];
    up[r]  = a + unb[0];
    inx[r] = 1.f / fmaxf(sqrtf(b), 1e-12f);
    iny[r] = 1.f / fmaxf(sqrtf(c), 1e-12f);
}

// ybar[b,d] = (1/T) sum_t YE[b,t,d] * invny[b*T+t]
__global__ void ybar_k(const float* __restrict__ YE, const float* __restrict__ iny,
                       float* __restrict__ YB)
{
    const int b = blockIdx.x, col = blockIdx.y * 128 + threadIdx.x;
    const float* p = YE + (size_t)b * 1024 * 768 + col;
    const float* w = iny + b * 1024;
    float s = 0.f;
    #pragma unroll 8
    for (int tt = 0; tt < 1024; ++tt) s += p[(size_t)tt * 768] * w[tt];
    YB[b * 768 + col] = s * (1.0f / 1024.0f);
}

__global__ void scores_k(const float* __restrict__ XE, const float* __restrict__ YB,
                         const float* __restrict__ invnx, const float* __restrict__ unpot,
                         const float* __restrict__ redw, float* __restrict__ sc)
{
    __shared__ float red[8];
    const int r = blockIdx.x, tid = threadIdx.x;
    const int b = r >> 10;
    const size_t base = (size_t)r * 768;
    const float* yb = YB + b * 768;
    float d = XE[base + tid] * yb[tid]
            + XE[base + tid + 256] * yb[tid + 256]
            + XE[base + tid + 512] * yb[tid + 512];
    #pragma unroll
    for (int o = 16; o; o >>= 1) d += __shfl_xor_sync(0xffffffffu, d, o);
    if ((tid & 31) == 0) red[tid >> 5] = d;
    __syncthreads();
    if (tid == 0) {
        float D = 0.f;
        #pragma unroll
        for (int i = 0; i < 8; i++) D += red[i];
        sc[r] = redw[0] * unpot[r] + redw[1] * (D * invnx[r]);
    }
}

__global__ void final_k(const float* __restrict__ U, const float* __restrict__ sc,
                        float* __restrict__ out)
{
    __shared__ float wsh[1024];
    __shared__ float red[8];
    __shared__ float finv;
    const int b = blockIdx.x, tid = threadIdx.x;
    float l0 = sc[b * 1024 + tid];
    float l1 = sc[b * 1024 + tid + 256];
    float l2 = sc[b * 1024 + tid + 512];
    float l3 = sc[b * 1024 + tid + 768];
    float mx = fmaxf(fmaxf(l0, l1), fmaxf(l2, l3));
    #pragma unroll
    for (int o = 16; o; o >>= 1) mx = fmaxf(mx, __shfl_xor_sync(0xffffffffu, mx, o));
    if ((tid & 31) == 0) red[tid >> 5] = mx;
    __syncthreads();
    if (tid == 0) {
        float M = red[0];
        #pragma unroll
        for (int i = 1; i < 8; i++) M = fmaxf(M, red[i]);
        finv = M;
    }
    __syncthreads();
    const float M = finv;
    __syncthreads();
    l0 = expf(l0 - M); l1 = expf(l1 - M); l2 = expf(l2 - M); l3 = expf(l3 - M);
    float s = l0 + l1 + l2 + l3;
    #pragma unroll
    for (int o = 16; o; o >>= 1) s += __shfl_xor_sync(0xffffffffu, s, o);
    if ((tid & 31) == 0) red[tid >> 5] = s;
    __syncthreads();
    if (tid == 0) {
        float S = 0.f;
        #pragma unroll
        for (int i = 0; i < 8; i++) S += red[i];
        finv = 1.f / S;
    }
    __syncthreads();
    const float inv = finv;
    wsh[tid]       = l0 * inv;
    wsh[tid + 256] = l1 * inv;
    wsh[tid + 512] = l2 * inv;
    wsh[tid + 768] = l3 * inv;
    __syncthreads();
    const float* Ub = U + (size_t)b * 1024 * 768;
    float a0 = 0.f, a1 = 0.f, a2 = 0.f;
    #pragma unroll 4
    for (int tt = 0; tt < 1024; ++tt) {
        const float wt = wsh[tt];
        const float* row = Ub + (size_t)tt * 768;
        a0 += wt * row[tid];
        a1 += wt * row[tid + 256];
        a2 += wt * row[tid + 512];
    }
    out[b * 768 + tid]       = a0;
    out[b * 768 + tid + 256] = a1;
    out[b * 768 + tid + 512] = a2;
}

// ---------------------------------------------------------------------------
extern "C" void kernel_launch(void* const* d_in, const int* in_sizes, int n_in,
                              void* d_out, int out_size)
{
    (void)in_sizes; (void)n_in; (void)out_size;
    const float* x        = (const float*)d_in[0];
    const float* fc1_b    = (const float*)d_in[2];
    const float* fc2_b    = (const float*)d_in[4];
    const float* un_emb_b = (const float*)d_in[6];
    const float* un_red_w = (const float*)d_in[7];
    const float* un_red_b = (const float*)d_in[8];
    const float* pw_x_b   = (const float*)d_in[10];
    const float* pw_y_b   = (const float*)d_in[12];
    const float* red_w    = (const float*)d_in[13];
    float* out = (float*)d_out;

    float *X, *H, *U, *XE, *YE, *W1, *W2, *Wc, *PT, *YB, *UP, *INX, *INY, *SC;
    cudaGetSymbolAddress((void**)&X,   g_X);
    cudaGetSymbolAddress((void**)&H,   g_H);
    cudaGetSymbolAddress((void**)&U,   g_U);
    cudaGetSymbolAddress((void**)&XE,  g_XE);
    cudaGetSymbolAddress((void**)&YE,  g_YE);
    cudaGetSymbolAddress((void**)&W1,  g_W1);
    cudaGetSymbolAddress((void**)&W2,  g_W2);
    cudaGetSymbolAddress((void**)&Wc,  g_Wc);
    cudaGetSymbolAddress((void**)&PT,  g_PT);
    cudaGetSymbolAddress((void**)&YB,  g_YB);
    cudaGetSymbolAddress((void**)&UP,  g_UP);
    cudaGetSymbolAddress((void**)&INX, g_INX);
    cudaGetSymbolAddress((void**)&INY, g_INY);
    cudaGetSymbolAddress((void**)&SC,  g_SC);

    cudaFuncSetAttribute((const void*)gemm_tf32<true,  true >, cudaFuncAttributeMaxDynamicSharedMemorySize, GSMEM);
    cudaFuncSetAttribute((const void*)gemm_tf32<false, true >, cudaFuncAttributeMaxDynamicSharedMemorySize, GSMEM);
    cudaFuncSetAttribute((const void*)gemm_fused3, cudaFuncAttributeMaxDynamicSharedMemorySize, GSMEM);

    // pre-round x + weights (W3/W4/W5 rounded directly into concat Wc)
    round_k<<<Mn * INn / 4 / 256, 256>>>((const float4*)x, (float4*)X, Mn * INn / 4);
    {
        RoundBatch rb;
        const int n1 = INn * INn / 4, n2 = Dn * INn / 4, n3 = Dn * Dn / 4;
        rb.s[0] = (const float4*)d_in[1];  rb.d[0] = (float4*)W1;
        rb.s[1] = (const float4*)d_in[3];  rb.d[1] = (float4*)W2;
        rb.s[2] = (const float4*)d_in[5];  rb.d[2] = (float4*)Wc;
        rb.s[3] = (const float4*)d_in[9];  rb.d[3] = (float4*)(Wc + (size_t)Dn * Dn);
        rb.s[4] = (const float4*)d_in[11]; rb.d[4] = (float4*)(Wc + (size_t)2 * Dn * Dn);
        rb.off[0] = 0; rb.off[1] = n1; rb.off[2] = n1 + n2;
        rb.off[3] = rb.off[2] + n3; rb.off[4] = rb.off[3] + n3; rb.off[5] = rb.off[4] + n3;
        round_batch_k<<<(rb.off[5] + 255) / 256, 256>>>(rb);
    }

    // 1. H = round(relu(X @ W1^T + b))   [32768 x 1536], K=1536
    gemm_tf32<true, true><<<dim3(12, 256), 256, GSMEM>>>(X, W1, fc1_b, H, 1536, 1536);
    // 2. U = round(H @ W2^T + b)         [32768 x 768], K=1536
    gemm_tf32<false, true><<<dim3(6, 256), 256, GSMEM>>>(H, W2, fc2_b, U, 768, 1536);
    // 3. fused E|XE|YE                   [32768 x 2304], K=768; E never stored
    gemm_fused3<<<dim3(18, 256), 256, GSMEM>>>(U, Wc, un_emb_b, pw_x_b, pw_y_b,
                                               un_red_w, XE, YE, PT);
    // 4-7. combine partials, ybar, scores, softmax-weighted sum
    combine_k<<<Mn / 256, 256>>>(PT, un_red_b, UP, INX, INY);
    ybar_k<<<dim3(Bn, 6), 128>>>(YE, INY, YB);
    scores_k<<<Mn, 256>>>(XE, YB, INX, UP, red_w, SC);
    final_k<<<Bn, 256>>>(U, SC, out);
}

// round 12
// speedup vs baseline: 1.6451x; 1.0552x over previous
#include <cuda_runtime.h>
#include <cstdint>
#include <cstddef>

namespace {
constexpr int Bn = 32, Tn = 1024, INn = 1536, Dn = 768;
constexpr int Mn = Bn * Tn;  // 32768
constexpr int GSMEM = 48 * 1024;  // 2 stages x (A 16KB + B 8KB)
}

// Scratch (static __device__ globals: allocation-free rule)
__device__ __align__(256) float g_X [(size_t)Mn * INn];
__device__ __align__(256) float g_H [(size_t)Mn * INn];
__device__ __align__(256) float g_U [(size_t)Mn * Dn];
__device__ __align__(256) float g_XE[(size_t)Mn * Dn];
__device__ __align__(256) float g_YE[(size_t)Mn * Dn];
__device__ __align__(256) float g_W1[(size_t)INn * INn];
__device__ __align__(256) float g_W2[(size_t)Dn * INn];
__device__ __align__(256) float g_Wc[(size_t)3 * Dn * Dn];   // [2304 x 768] concat W3|W4|W5
__device__ __align__(256) float g_PT[(size_t)36 * Mn];       // per-(nblock,row) partials
__device__ __align__(256) float g_YB[Bn * Dn];
__device__ __align__(256) float g_UP[Mn];
__device__ __align__(256) float g_INX[Mn];
__device__ __align__(256) float g_INY[Mn];
__device__ __align__(256) float g_SC[Mn];

// ---------------------------------------------------------------------------
// helpers
// ---------------------------------------------------------------------------
__device__ __forceinline__ uint32_t smem_u32(const void* p) {
    uint32_t a;
    asm("{ .reg .u64 t; cvta.to.shared.u64 t, %1; cvt.u32.u64 %0, t; }" : "=r"(a) : "l"(p));
    return a;
}
__device__ __forceinline__ void cp16(float* s, const float* g) {
    uint32_t sa = (uint32_t)__cvta_generic_to_shared(s);
    asm volatile("cp.async.cg.shared.global [%0], [%1], 16;\n" :: "r"(sa), "l"(g));
}
__device__ __forceinline__ void cp_commit() { asm volatile("cp.async.commit_group;\n"); }
template <int NW> __device__ __forceinline__ void cp_wait() {
    asm volatile("cp.async.wait_group %0;\n" :: "n"(NW));
}
__device__ __forceinline__ uint32_t f2tf(float x) {
    uint32_t r;
    asm("cvt.rna.tf32.f32 %0, %1;\n" : "=r"(r) : "f"(x));
    return r;
}
__device__ __forceinline__ void mma8(float* c, const uint32_t* a, const uint32_t* b) {
    asm volatile(
        "mma.sync.aligned.m16n8k8.row.col.f32.tf32.tf32.f32 "
        "{%0,%1,%2,%3}, {%4,%5,%6,%7}, {%8,%9}, {%0,%1,%2,%3};\n"
        : "+f"(c[0]), "+f"(c[1]), "+f"(c[2]), "+f"(c[3])
        : "r"(a[0]), "r"(a[1]), "r"(a[2]), "r"(a[3]), "r"(b[0]), "r"(b[1]));
}
__device__ __forceinline__ void ldsm4(uint32_t* r, uint32_t addr) {
    asm volatile("ldmatrix.sync.aligned.m8n8.x4.shared.b16 {%0,%1,%2,%3}, [%4];"
                 : "=r"(r[0]), "=r"(r[1]), "=r"(r[2]), "=r"(r[3]) : "r"(addr));
}
__device__ __forceinline__ void ldsm2(uint32_t* r, uint32_t addr) {
    asm volatile("ldmatrix.sync.aligned.m8n8.x2.shared.b16 {%0,%1}, [%2];"
                 : "=r"(r[0]), "=r"(r[1]) : "r"(addr));
}

__global__ void round_k(const float4* __restrict__ src, float4* __restrict__ dst, int n4)
{
    int i = blockIdx.x * 256 + threadIdx.x;
    if (i >= n4) return;
    float4 v = src[i];
    v.x = __uint_as_float(f2tf(v.x)); v.y = __uint_as_float(f2tf(v.y));
    v.z = __uint_as_float(f2tf(v.z)); v.w = __uint_as_float(f2tf(v.w));
    dst[i] = v;
}
struct RoundBatch { const float4* s[5]; float4* d[5]; int off[6]; };
__global__ void round_batch_k(RoundBatch rb)
{
    int i = blockIdx.x * 256 + threadIdx.x;
    #pragma unroll
    for (int j = 0; j < 5; j++) {
        if (i >= rb.off[j] && i < rb.off[j + 1]) {
            int k = i - rb.off[j];
            float4 v = rb.s[j][k];
            v.x = __uint_as_float(f2tf(v.x)); v.y = __uint_as_float(f2tf(v.y));
            v.z = __uint_as_float(f2tf(v.z)); v.w = __uint_as_float(f2tf(v.w));
            rb.d[j][k] = v;
        }
    }
}

// ---------------------------------------------------------------------------
// GEMM core: CTA 128(M)x64(N)x32, 128 threads, 4 warps 2(m)x2(n), warp tile
// 64x32 (proven R5 fragment geometry), 2-stage dual-sync cp.async pipeline.
// 4 CTAs/SM -> 4 independent barrier domains.
// SMEM floats: A stage s at s*4096 (16KB), B stage s at 8192+s*2048 (8KB).
// ---------------------------------------------------------------------------
#define GEMM_PREAMBLE_AND_MAINLOOP(APTR, WPTR, KVAL)                                    \
    extern __shared__ float smem[];                                                     \
    const int tid  = threadIdx.x;                                                       \
    const int lane = tid & 31, wrp = tid >> 5;                                          \
    const int wm = wrp >> 1, wn = wrp & 1;                                              \
    const int m0 = blockIdx.y * 128, n0 = blockIdx.x * 64;                              \
    const int c4 = tid & 7, rb = tid >> 3;                                              \
    const int soff = rb * 32 + ((c4 ^ (rb & 7)) << 2);                                  \
    const float* gA = (APTR) + (size_t)(m0 + rb) * (KVAL) + c4 * 4;                     \
    const float* gW = (WPTR) + (size_t)(n0 + rb) * (KVAL) + c4 * 4;                     \
    const uint32_t smb = smem_u32(smem);                                                \
    const int s7 = lane & 7;                                                            \
    const int half  = (lane >> 3) & 1;                                                  \
    const int koffA = lane >> 4;                                                        \
    const int koffB = (lane >> 3) & 1;                                                  \
    uint32_t rowA[4], rowB[4];                                                          \
    _Pragma("unroll")                                                                   \
    for (int mf = 0; mf < 4; mf++)                                                      \
        rowA[mf] = (uint32_t)(wm * 64 + mf * 16 + half * 8 + s7) * 128u;                \
    _Pragma("unroll")                                                                   \
    for (int nf = 0; nf < 4; nf++)                                                      \
        rowB[nf] = (uint32_t)(wn * 32 + nf * 8 + s7) * 128u;                            \
    float acc[4][4][4];                                                                 \
    _Pragma("unroll")                                                                   \
    for (int i = 0; i < 4; i++)                                                         \
        _Pragma("unroll")                                                               \
        for (int j = 0; j < 4; j++)                                                     \
            _Pragma("unroll")                                                           \
            for (int q = 0; q < 4; q++) acc[i][j][q] = 0.f;                             \
    const int kiters = (KVAL) >> 5;                                                     \
    _Pragma("unroll")                                                                   \
    for (int p = 0; p < 8; p++) cp16(&smem[soff + p * 512], gA + (size_t)p * 16 * (KVAL)); \
    _Pragma("unroll")                                                                   \
    for (int p = 0; p < 4; p++) cp16(&smem[8192 + soff + p * 512], gW + (size_t)p * 16 * (KVAL)); \
    cp_commit();                                                                        \
    for (int it = 0; it < kiters; ++it) {                                               \
        const int st = it & 1;                                                          \
        if (it + 1 < kiters) {                                                          \
            const int k0  = (it + 1) << 5;                                              \
            const int stn = (it + 1) & 1;                                               \
            _Pragma("unroll")                                                           \
            for (int p = 0; p < 8; p++)                                                 \
                cp16(&smem[stn * 4096 + soff + p * 512], gA + k0 + (size_t)p * 16 * (KVAL)); \
            _Pragma("unroll")                                                           \
            for (int p = 0; p < 4; p++)                                                 \
                cp16(&smem[8192 + stn * 2048 + soff + p * 512], gW + k0 + (size_t)p * 16 * (KVAL)); \
            cp_commit();                                                                \
            cp_wait<1>();                                                               \
        } else {                                                                        \
            cp_wait<0>();                                                               \
        }                                                                               \
        __syncthreads();                                                                \
        const uint32_t stA = smb + (uint32_t)st * 16384u;                               \
        const uint32_t stB = smb + 32768u + (uint32_t)st * 8192u;                       \
        _Pragma("unroll")                                                               \
        for (int kk4 = 0; kk4 < 8; kk4 += 2) {                                          \
            const uint32_t colA = (uint32_t)(((kk4 + koffA) ^ s7) << 4);                \
            const uint32_t colB = (uint32_t)(((kk4 + koffB) ^ s7) << 4);                \
            uint32_t af[4][4], bf[4][2];                                                \
            _Pragma("unroll")                                                           \
            for (int mf = 0; mf < 4; mf++) ldsm4(af[mf], stA + rowA[mf] + colA);        \
            _Pragma("unroll")                                                           \
            for (int nf = 0; nf < 4; nf++) ldsm2(bf[nf], stB + rowB[nf] + colB);        \
            _Pragma("unroll")                                                           \
            for (int mf = 0; mf < 4; mf++)                                              \
                _Pragma("unroll")                                                       \
                for (int nf = 0; nf < 4; nf++)                                          \
                    mma8(acc[mf][nf], af[mf], bf[nf]);                                  \
        }                                                                               \
        __syncthreads();                                                                \
    }

// loader note: B tile is 64 rows; threads rb 0..15 load rows rb+16p, p=0..3.

// Plain GEMM: C = A@W^T + bias, optional relu / tf32-round of outputs (fc1/fc2)
template <bool RELU, bool ROUND>
__global__ __launch_bounds__(128, 4) void gemm_tf32(
    const float* __restrict__ A, const float* __restrict__ W,
    const float* __restrict__ bias, float* __restrict__ C,
    int N, int K)
{
    GEMM_PREAMBLE_AND_MAINLOOP(A, W, K)

    const int g = lane >> 2, t = lane & 3;
    #pragma unroll
    for (int mf = 0; mf < 4; mf++) {
        const int row = m0 + wm * 64 + mf * 16 + g;
        #pragma unroll
        for (int nf = 0; nf < 4; nf++) {
            const int col = n0 + wn * 32 + nf * 8 + 2 * t;
            const float b0 = bias[col], b1 = bias[col + 1];
            float v0 = acc[mf][nf][0] + b0;
            float v1 = acc[mf][nf][1] + b1;
            float v2 = acc[mf][nf][2] + b0;
            float v3 = acc[mf][nf][3] + b1;
            if (RELU) {
                v0 = fmaxf(v0, 0.f); v1 = fmaxf(v1, 0.f);
                v2 = fmaxf(v2, 0.f); v3 = fmaxf(v3, 0.f);
            }
            if (ROUND) {
                v0 = __uint_as_float(f2tf(v0)); v1 = __uint_as_float(f2tf(v1));
                v2 = __uint_as_float(f2tf(v2)); v3 = __uint_as_float(f2tf(v3));
            }
            *(float2*)(C + (size_t)row       * N + col) = make_float2(v0, v1);
            *(float2*)(C + (size_t)(row + 8) * N + col) = make_float2(v2, v3);
        }
    }
}

// Fused D-GEMM: N=2304 concat [E | XE | YE] against Wc; 36 n-blocks, 12/seg.
// seg 0: E = relu(.+b_e); reduce E·unred per row -> partials, no store.
// seg 1: XE store + x^2 partials. seg 2: YE store + y^2 partials.
// Deterministic smem tree: part2[128][9] (2 wn x 4 t), 8-way sum -> PT.
__global__ __launch_bounds__(128, 4) void gemm_fused3(
    const float* __restrict__ A, const float* __restrict__ W,
    const float* __restrict__ b_e, const float* __restrict__ b_x,
    const float* __restrict__ b_y, const float* __restrict__ unred,
    float* __restrict__ XE, float* __restrict__ YE, float* __restrict__ PT)
{
    GEMM_PREAMBLE_AND_MAINLOOP(A, W, 768)

    const int g = lane >> 2, t = lane & 3;
    const int seg = blockIdx.x / 12;             // 0:E 1:XE 2:YE
    const float* bias = (seg == 0) ? b_e : (seg == 1) ? b_x : b_y;
    float* Cseg = (seg == 1) ? XE : YE;
    const int cb0 = (blockIdx.x - seg * 12) * 64 + wn * 32;  // segment-local col base

    float* part2 = smem;   // mainloop ended with __syncthreads: stages dead

    #pragma unroll
    for (int mf = 0; mf < 4; mf++) {
        const int row = wm * 64 + mf * 16 + g;   // CTA-local row
        float ps0 = 0.f, ps1 = 0.f;
        #pragma unroll
        for (int nf = 0; nf < 4; nf++) {
            const int cs = cb0 + nf * 8 + 2 * t;
            const float b0 = bias[cs], b1 = bias[cs + 1];
            float v0 = acc[mf][nf][0] + b0;
            float v1 = acc[mf][nf][1] + b1;
            float v2 = acc[mf][nf][2] + b0;
            float v3 = acc[mf][nf][3] + b1;
            if (seg == 0) {
                v0 = fmaxf(v0, 0.f); v1 = fmaxf(v1, 0.f);
                v2 = fmaxf(v2, 0.f); v3 = fmaxf(v3, 0.f);
                const float w0 = unred[cs], w1 = unred[cs + 1];
                ps0 += v0 * w0 + v1 * w1;
                ps1 += v2 * w0 + v3 * w1;
            } else {
                ps0 += v0 * v0 + v1 * v1;
                ps1 += v2 * v2 + v3 * v3;
                *(float2*)(Cseg + (size_t)(m0 + row)     * 768 + cs) = make_float2(v0, v1);
                *(float2*)(Cseg + (size_t)(m0 + row + 8) * 768 + cs) = make_float2(v2, v3);
            }
        }
        part2[row * 9 + wn * 4 + t]       = ps0;
        part2[(row + 8) * 9 + wn * 4 + t] = ps1;
    }
    __syncthreads();
    if (tid < 128) {
        float s = 0.f;
        #pragma unroll
        for (int c = 0; c < 8; c++) s += part2[tid * 9 + c];
        PT[(size_t)blockIdx.x * Mn + m0 + tid] = s;
    }
}

// --------------------------- tail kernels ----------------------------------
__global__ void combine_k(const float* __restrict__ PT, const float* __restrict__ unb,
                          float* __restrict__ up, float* __restrict__ inx,
                          float* __restrict__ iny)
{
    const int r = blockIdx.x * 256 + threadIdx.x;
    float a = 0.f, b = 0.f, c = 0.f;
    #pragma unroll
    for (int nb = 0; nb < 12; nb++)  a += PT[(size_t)nb * Mn + r];
    #pragma unroll
    for (int nb = 12; nb < 24; nb++) b += PT[(size_t)nb * Mn + r];
    #pragma unroll
    for (int nb = 24; nb < 36; nb++) c += PT[(size_t)nb * Mn + r];
    up[r]  = a + unb[0];
    inx[r] = 1.f / fmaxf(sqrtf(b), 1e-12f);
    iny[r] = 1.f / fmaxf(sqrtf(c), 1e-12f);
}

// ybar[b,d] = (1/T) sum_t YE[b,t,d] * invny[b*T+t]
__global__ void ybar_k(const float* __restrict__ YE, const float* __restrict__ iny,
                       float* __restrict__ YB)
{
    const int b = blockIdx.x, col = blockIdx.y * 128 + threadIdx.x;
    const float* p = YE + (size_t)b * 1024 * 768 + col;
    const float* w = iny + b * 1024;
    float s = 0.f;
    #pragma unroll 8
    for (int tt = 0; tt < 1024; ++tt) s += p[(size_t)tt * 768] * w[tt];
    YB[b * 768 + col] = s * (1.0f / 1024.0f);
}

__global__ void scores_k(const float* __restrict__ XE, const float* __restrict__ YB,
                         const float* __restrict__ invnx, const float* __restrict__ unpot,
                         const float* __restrict__ redw, float* __restrict__ sc)
{
    __shared__ float red[8];
    const int r = blockIdx.x, tid = threadIdx.x;
    const int b = r >> 10;
    const size_t base = (size_t)r * 768;
    const float* yb = YB + b * 768;
    float d = XE[base + tid] * yb[tid]
            + XE[base + tid + 256] * yb[tid + 256]
            + XE[base + tid + 512] * yb[tid + 512];
    #pragma unroll
    for (int o = 16; o; o >>= 1) d += __shfl_xor_sync(0xffffffffu, d, o);
    if ((tid & 31) == 0) red[tid >> 5] = d;
    __syncthreads();
    if (tid == 0) {
        float D = 0.f;
        #pragma unroll
        for (int i = 0; i < 8; i++) D += red[i];
        sc[r] = redw[0] * unpot[r] + redw[1] * (D * invnx[r]);
    }
}

__global__ void final_k(const float* __restrict__ U, const float* __restrict__ sc,
                        float* __restrict__ out)
{
    __shared__ float wsh[1024];
    __shared__ float red[8];
    __shared__ float finv;
    const int b = blockIdx.x, tid = threadIdx.x;
    float l0 = sc[b * 1024 + tid];
    float l1 = sc[b * 1024 + tid + 256];
    float l2 = sc[b * 1024 + tid + 512];
    float l3 = sc[b * 1024 + tid + 768];
    float mx = fmaxf(fmaxf(l0, l1), fmaxf(l2, l3));
    #pragma unroll
    for (int o = 16; o; o >>= 1) mx = fmaxf(mx, __shfl_xor_sync(0xffffffffu, mx, o));
    if ((tid & 31) == 0) red[tid >> 5] = mx;
    __syncthreads();
    if (tid == 0) {
        float M = red[0];
        #pragma unroll
        for (int i = 1; i < 8; i++) M = fmaxf(M, red[i]);
        finv = M;
    }
    __syncthreads();
    const float M = finv;
    __syncthreads();
    l0 = expf(l0 - M); l1 = expf(l1 - M); l2 = expf(l2 - M); l3 = expf(l3 - M);
    float s = l0 + l1 + l2 + l3;
    #pragma unroll
    for (int o = 16; o; o >>= 1) s += __shfl_xor_sync(0xffffffffu, s, o);
    if ((tid & 31) == 0) red[tid >> 5] = s;
    __syncthreads();
    if (tid == 0) {
        float S = 0.f;
        #pragma unroll
        for (int i = 0; i < 8; i++) S += red[i];
        finv = 1.f / S;
    }
    __syncthreads();
    const float inv = finv;
    wsh[tid]       = l0 * inv;
    wsh[tid + 256] = l1 * inv;
    wsh[tid + 512] = l2 * inv;
    wsh[tid + 768] = l3 * inv;
    __syncthreads();
    const float* Ub = U + (size_t)b * 1024 * 768;
    float a0 = 0.f, a1 = 0.f, a2 = 0.f;
    #pragma unroll 4
    for (int tt = 0; tt < 1024; ++tt) {
        const float wt = wsh[tt];
        const float* row = Ub + (size_t)tt * 768;
        a0 += wt * row[tid];
        a1 += wt * row[tid + 256];
        a2 += wt * row[tid + 512];
    }
    out[b * 768 + tid]       = a0;
    out[b * 768 + tid + 256] = a1;
    out[b * 768 + tid + 512] = a2;
}

// ---------------------------------------------------------------------------
extern "C" void kernel_launch(void* const* d_in, const int* in_sizes, int n_in,
                              void* d_out, int out_size)
{
    (void)in_sizes; (void)n_in; (void)out_size;
    const float* x        = (const float*)d_in[0];
    const float* fc1_b    = (const float*)d_in[2];
    const float* fc2_b    = (const float*)d_in[4];
    const float* un_emb_b = (const float*)d_in[6];
    const float* un_red_w = (const float*)d_in[7];
    const float* un_red_b = (const float*)d_in[8];
    const float* pw_x_b   = (const float*)d_in[10];
    const float* pw_y_b   = (const float*)d_in[12];
    const float* red_w    = (const float*)d_in[13];
    float* out = (float*)d_out;

    float *X, *H, *U, *XE, *YE, *W1, *W2, *Wc, *PT, *YB, *UP, *INX, *INY, *SC;
    cudaGetSymbolAddress((void**)&X,   g_X);
    cudaGetSymbolAddress((void**)&H,   g_H);
    cudaGetSymbolAddress((void**)&U,   g_U);
    cudaGetSymbolAddress((void**)&XE,  g_XE);
    cudaGetSymbolAddress((void**)&YE,  g_YE);
    cudaGetSymbolAddress((void**)&W1,  g_W1);
    cudaGetSymbolAddress((void**)&W2,  g_W2);
    cudaGetSymbolAddress((void**)&Wc,  g_Wc);
    cudaGetSymbolAddress((void**)&PT,  g_PT);
    cudaGetSymbolAddress((void**)&YB,  g_YB);
    cudaGetSymbolAddress((void**)&UP,  g_UP);
    cudaGetSymbolAddress((void**)&INX, g_INX);
    cudaGetSymbolAddress((void**)&INY, g_INY);
    cudaGetSymbolAddress((void**)&SC,  g_SC);

    cudaFuncSetAttribute((const void*)gemm_tf32<true,  true >, cudaFuncAttributeMaxDynamicSharedMemorySize, GSMEM);
    cudaFuncSetAttribute((const void*)gemm_tf32<false, true >, cudaFuncAttributeMaxDynamicSharedMemorySize, GSMEM);
    cudaFuncSetAttribute((const void*)gemm_fused3, cudaFuncAttributeMaxDynamicSharedMemorySize, GSMEM);

    // pre-round x + weights (W3/W4/W5 rounded directly into concat Wc)
    round_k<<<Mn * INn / 4 / 256, 256>>>((const float4*)x, (float4*)X, Mn * INn / 4);
    {
        RoundBatch rb;
        const int n1 = INn * INn / 4, n2 = Dn * INn / 4, n3 = Dn * Dn / 4;
        rb.s[0] = (const float4*)d_in[1];  rb.d[0] = (float4*)W1;
        rb.s[1] = (const float4*)d_in[3];  rb.d[1] = (float4*)W2;
        rb.s[2] = (const float4*)d_in[5];  rb.d[2] = (float4*)Wc;
        rb.s[3] = (const float4*)d_in[9];  rb.d[3] = (float4*)(Wc + (size_t)Dn * Dn);
        rb.s[4] = (const float4*)d_in[11]; rb.d[4] = (float4*)(Wc + (size_t)2 * Dn * Dn);
        rb.off[0] = 0; rb.off[1] = n1; rb.off[2] = n1 + n2;
        rb.off[3] = rb.off[2] + n3; rb.off[4] = rb.off[3] + n3; rb.off[5] = rb.off[4] + n3;
        round_batch_k<<<(rb.off[5] + 255) / 256, 256>>>(rb);
    }

    // 1. H = round(relu(X @ W1^T + b))   [32768 x 1536], K=1536
    gemm_tf32<true, true><<<dim3(24, 256), 128, GSMEM>>>(X, W1, fc1_b, H, 1536, 1536);
    // 2. U = round(H @ W2^T + b)         [32768 x 768], K=1536
    gemm_tf32<false, true><<<dim3(12, 256), 128, GSMEM>>>(H, W2, fc2_b, U, 768, 1536);
    // 3. fused E|XE|YE                   [32768 x 2304], K=768; E never stored
    gemm_fused3<<<dim3(36, 256), 128, GSMEM>>>(U, Wc, un_emb_b, pw_x_b, pw_y_b,
                                               un_red_w, XE, YE, PT);
    // 4-7. combine partials, ybar, scores, softmax-weighted sum
    combine_k<<<Mn / 256, 256>>>(PT, un_red_b, UP, INX, INY);
    ybar_k<<<dim3(Bn, 6), 128>>>(YE, INY, YB);
    scores_k<<<Mn, 256>>>(XE, YB, INX, UP, red_w, SC);
    final_k<<<Bn, 256>>>(U, SC, out);
}

// round 13
// speedup vs baseline: 1.8915x; 1.1498x over previous
#include <cuda_runtime.h>
#include <cstdint>
#include <cstddef>

namespace {
constexpr int Bn = 32, Tn = 1024, INn = 1536, Dn = 768;
constexpr int Mn = Bn * Tn;  // 32768
constexpr int GSMEM = 48 * 1024;  // 2 stages x (A 16KB + B 8KB)
}

// Scratch (static __device__ globals: allocation-free rule)
__device__ __align__(256) float g_H [(size_t)Mn * INn];
__device__ __align__(256) float g_U [(size_t)Mn * Dn];
__device__ __align__(256) float g_XE[(size_t)Mn * Dn];
__device__ __align__(256) float g_YE[(size_t)Mn * Dn];
__device__ __align__(256) float g_W1[(size_t)INn * INn];
__device__ __align__(256) float g_W2[(size_t)Dn * INn];
__device__ __align__(256) float g_Wc[(size_t)3 * Dn * Dn];   // [2304 x 768] concat W3|W4|W5
__device__ __align__(256) float g_PT[(size_t)36 * Mn];       // fused3 per-(nblock,row) partials
__device__ __align__(256) float g_PTY[(size_t)Bn * 8 * Dn];  // ybar t-slice partials
__device__ __align__(256) float g_PTF[(size_t)Bn * 8 * Dn];  // final t-slice partials
__device__ __align__(256) float g_WS[Mn];                    // softmax weights
__device__ __align__(256) float g_YB[Bn * Dn];
__device__ __align__(256) float g_UP[Mn];
__device__ __align__(256) float g_INX[Mn];
__device__ __align__(256) float g_INY[Mn];
__device__ __align__(256) float g_SC[Mn];

// ---------------------------------------------------------------------------
// helpers
// ---------------------------------------------------------------------------
__device__ __forceinline__ uint32_t smem_u32(const void* p) {
    uint32_t a;
    asm("{ .reg .u64 t; cvta.to.shared.u64 t, %1; cvt.u32.u64 %0, t; }" : "=r"(a) : "l"(p));
    return a;
}
__device__ __forceinline__ void cp16(float* s, const float* g) {
    uint32_t sa = (uint32_t)__cvta_generic_to_shared(s);
    asm volatile("cp.async.cg.shared.global [%0], [%1], 16;\n" :: "r"(sa), "l"(g));
}
__device__ __forceinline__ void cp_commit() { asm volatile("cp.async.commit_group;\n"); }
template <int NW> __device__ __forceinline__ void cp_wait() {
    asm volatile("cp.async.wait_group %0;\n" :: "n"(NW));
}
__device__ __forceinline__ uint32_t f2tf(float x) {
    uint32_t r;
    asm("cvt.rna.tf32.f32 %0, %1;\n" : "=r"(r) : "f"(x));
    return r;
}
__device__ __forceinline__ void mma8(float* c, const uint32_t* a, const uint32_t* b) {
    asm volatile(
        "mma.sync.aligned.m16n8k8.row.col.f32.tf32.tf32.f32 "
        "{%0,%1,%2,%3}, {%4,%5,%6,%7}, {%8,%9}, {%0,%1,%2,%3};\n"
        : "+f"(c[0]), "+f"(c[1]), "+f"(c[2]), "+f"(c[3])
        : "r"(a[0]), "r"(a[1]), "r"(a[2]), "r"(a[3]), "r"(b[0]), "r"(b[1]));
}
__device__ __forceinline__ void ldsm4(uint32_t* r, uint32_t addr) {
    asm volatile("ldmatrix.sync.aligned.m8n8.x4.shared.b16 {%0,%1,%2,%3}, [%4];"
                 : "=r"(r[0]), "=r"(r[1]), "=r"(r[2]), "=r"(r[3]) : "r"(addr));
}
__device__ __forceinline__ void ldsm2(uint32_t* r, uint32_t addr) {
    asm volatile("ldmatrix.sync.aligned.m8n8.x2.shared.b16 {%0,%1}, [%2];"
                 : "=r"(r[0]), "=r"(r[1]) : "r"(addr));
}

struct RoundBatch { const float4* s[5]; float4* d[5]; int off[6]; };
__global__ void round_batch_k(RoundBatch rb)
{
    int i = blockIdx.x * 256 + threadIdx.x;
    #pragma unroll
    for (int j = 0; j < 5; j++) {
        if (i >= rb.off[j] && i < rb.off[j + 1]) {
            int k = i - rb.off[j];
            float4 v = rb.s[j][k];
            v.x = __uint_as_float(f2tf(v.x)); v.y = __uint_as_float(f2tf(v.y));
            v.z = __uint_as_float(f2tf(v.z)); v.w = __uint_as_float(f2tf(v.w));
            rb.d[j][k] = v;
        }
    }
}

// ---------------------------------------------------------------------------
// GEMM core (R12 proven): CTA 128(M)x64(N)x32, 128 threads, 4 warps 2x2,
// warp tile 64x32, 2-stage dual-sync cp.async pipeline, 4 CTAs/SM.
// SMEM floats: A stage s at s*4096 (16KB), B stage s at 8192+s*2048 (8KB).
// ---------------------------------------------------------------------------
#define GEMM_PREAMBLE_AND_MAINLOOP(APTR, WPTR, KVAL)                                    \
    extern __shared__ float smem[];                                                     \
    const int tid  = threadIdx.x;                                                       \
    const int lane = tid & 31, wrp = tid >> 5;                                          \
    const int wm = wrp >> 1, wn = wrp & 1;                                              \
    const int m0 = blockIdx.y * 128, n0 = blockIdx.x * 64;                              \
    const int c4 = tid & 7, rb = tid >> 3;                                              \
    const int soff = rb * 32 + ((c4 ^ (rb & 7)) << 2);                                  \
    const float* gA = (APTR) + (size_t)(m0 + rb) * (KVAL) + c4 * 4;                     \
    const float* gW = (WPTR) + (size_t)(n0 + rb) * (KVAL) + c4 * 4;                     \
    const uint32_t smb = smem_u32(smem);                                                \
    const int s7 = lane & 7;                                                            \
    const int half  = (lane >> 3) & 1;                                                  \
    const int koffA = lane >> 4;                                                        \
    const int koffB = (lane >> 3) & 1;                                                  \
    uint32_t rowA[4], rowB[4];                                                          \
    _Pragma("unroll")                                                                   \
    for (int mf = 0; mf < 4; mf++)                                                      \
        rowA[mf] = (uint32_t)(wm * 64 + mf * 16 + half * 8 + s7) * 128u;                \
    _Pragma("unroll")                                                                   \
    for (int nf = 0; nf < 4; nf++)                                                      \
        rowB[nf] = (uint32_t)(wn * 32 + nf * 8 + s7) * 128u;                            \
    float acc[4][4][4];                                                                 \
    _Pragma("unroll")                                                                   \
    for (int i = 0; i < 4; i++)                                                         \
        _Pragma("unroll")                                                               \
        for (int j = 0; j < 4; j++)                                                     \
            _Pragma("unroll")                                                           \
            for (int q = 0; q < 4; q++) acc[i][j][q] = 0.f;                             \
    const int kiters = (KVAL) >> 5;                                                     \
    _Pragma("unroll")                                                                   \
    for (int p = 0; p < 8; p++) cp16(&smem[soff + p * 512], gA + (size_t)p * 16 * (KVAL)); \
    _Pragma("unroll")                                                                   \
    for (int p = 0; p < 4; p++) cp16(&smem[8192 + soff + p * 512], gW + (size_t)p * 16 * (KVAL)); \
    cp_commit();                                                                        \
    for (int it = 0; it < kiters; ++it) {                                               \
        const int st = it & 1;                                                          \
        if (it + 1 < kiters) {                                                          \
            const int k0  = (it + 1) << 5;                                              \
            const int stn = (it + 1) & 1;                                               \
            _Pragma("unroll")                                                           \
            for (int p = 0; p < 8; p++)                                                 \
                cp16(&smem[stn * 4096 + soff + p * 512], gA + k0 + (size_t)p * 16 * (KVAL)); \
            _Pragma("unroll")                                                           \
            for (int p = 0; p < 4; p++)                                                 \
                cp16(&smem[8192 + stn * 2048 + soff + p * 512], gW + k0 + (size_t)p * 16 * (KVAL)); \
            cp_commit();                                                                \
            cp_wait<1>();                                                               \
        } else {                                                                        \
            cp_wait<0>();                                                               \
        }                                                                               \
        __syncthreads();                                                                \
        const uint32_t stA = smb + (uint32_t)st * 16384u;                               \
        const uint32_t stB = smb + 32768u + (uint32_t)st * 8192u;                       \
        _Pragma("unroll")                                                               \
        for (int kk4 = 0; kk4 < 8; kk4 += 2) {                                          \
            const uint32_t colA = (uint32_t)(((kk4 + koffA) ^ s7) << 4);                \
            const uint32_t colB = (uint32_t)(((kk4 + koffB) ^ s7) << 4);                \
            uint32_t af[4][4], bf[4][2];                                                \
            _Pragma("unroll")                                                           \
            for (int mf = 0; mf < 4; mf++) ldsm4(af[mf], stA + rowA[mf] + colA);        \
            _Pragma("unroll")                                                           \
            for (int nf = 0; nf < 4; nf++) ldsm2(bf[nf], stB + rowB[nf] + colB);        \
            _Pragma("unroll")                                                           \
            for (int mf = 0; mf < 4; mf++)                                              \
                _Pragma("unroll")                                                       \
                for (int nf = 0; nf < 4; nf++)                                          \
                    mma8(acc[mf][nf], af[mf], bf[nf]);                                  \
        }                                                                               \
        __syncthreads();                                                                \
    }

// Plain GEMM: C = A@W^T + bias, optional relu / tf32-round of outputs (fc1/fc2)
template <bool RELU, bool ROUND>
__global__ __launch_bounds__(128, 4) void gemm_tf32(
    const float* __restrict__ A, const float* __restrict__ W,
    const float* __restrict__ bias, float* __restrict__ C,
    int N, int K)
{
    GEMM_PREAMBLE_AND_MAINLOOP(A, W, K)

    const int g = lane >> 2, t = lane & 3;
    #pragma unroll
    for (int mf = 0; mf < 4; mf++) {
        const int row = m0 + wm * 64 + mf * 16 + g;
        #pragma unroll
        for (int nf = 0; nf < 4; nf++) {
            const int col = n0 + wn * 32 + nf * 8 + 2 * t;
            const float b0 = bias[col], b1 = bias[col + 1];
            float v0 = acc[mf][nf][0] + b0;
            float v1 = acc[mf][nf][1] + b1;
            float v2 = acc[mf][nf][2] + b0;
            float v3 = acc[mf][nf][3] + b1;
            if (RELU) {
                v0 = fmaxf(v0, 0.f); v1 = fmaxf(v1, 0.f);
                v2 = fmaxf(v2, 0.f); v3 = fmaxf(v3, 0.f);
            }
            if (ROUND) {
                v0 = __uint_as_float(f2tf(v0)); v1 = __uint_as_float(f2tf(v1));
                v2 = __uint_as_float(f2tf(v2)); v3 = __uint_as_float(f2tf(v3));
            }
            *(float2*)(C + (size_t)row       * N + col) = make_float2(v0, v1);
            *(float2*)(C + (size_t)(row + 8) * N + col) = make_float2(v2, v3);
        }
    }
}

// Fused D-GEMM: N=2304 concat [E | XE | YE] against Wc; 36 n-blocks, 12/seg.
__global__ __launch_bounds__(128, 4) void gemm_fused3(
    const float* __restrict__ A, const float* __restrict__ W,
    const float* __restrict__ b_e, const float* __restrict__ b_x,
    const float* __restrict__ b_y, const float* __restrict__ unred,
    float* __restrict__ XE, float* __restrict__ YE, float* __restrict__ PT)
{
    GEMM_PREAMBLE_AND_MAINLOOP(A, W, 768)

    const int g = lane >> 2, t = lane & 3;
    const int seg = blockIdx.x / 12;             // 0:E 1:XE 2:YE
    const float* bias = (seg == 0) ? b_e : (seg == 1) ? b_x : b_y;
    float* Cseg = (seg == 1) ? XE : YE;
    const int cb0 = (blockIdx.x - seg * 12) * 64 + wn * 32;

    float* part2 = smem;   // mainloop ended with __syncthreads: stages dead

    #pragma unroll
    for (int mf = 0; mf < 4; mf++) {
        const int row = wm * 64 + mf * 16 + g;
        float ps0 = 0.f, ps1 = 0.f;
        #pragma unroll
        for (int nf = 0; nf < 4; nf++) {
            const int cs = cb0 + nf * 8 + 2 * t;
            const float b0 = bias[cs], b1 = bias[cs + 1];
            float v0 = acc[mf][nf][0] + b0;
            float v1 = acc[mf][nf][1] + b1;
            float v2 = acc[mf][nf][2] + b0;
            float v3 = acc[mf][nf][3] + b1;
            if (seg == 0) {
                v0 = fmaxf(v0, 0.f); v1 = fmaxf(v1, 0.f);
                v2 = fmaxf(v2, 0.f); v3 = fmaxf(v3, 0.f);
                const float w0 = unred[cs], w1 = unred[cs + 1];
                ps0 += v0 * w0 + v1 * w1;
                ps1 += v2 * w0 + v3 * w1;
            } else {
                ps0 += v0 * v0 + v1 * v1;
                ps1 += v2 * v2 + v3 * v3;
                *(float2*)(Cseg + (size_t)(m0 + row)     * 768 + cs) = make_float2(v0, v1);
                *(float2*)(Cseg + (size_t)(m0 + row + 8) * 768 + cs) = make_float2(v2, v3);
            }
        }
        part2[row * 9 + wn * 4 + t]       = ps0;
        part2[(row + 8) * 9 + wn * 4 + t] = ps1;
    }
    __syncthreads();
    if (tid < 128) {
        float s = 0.f;
        #pragma unroll
        for (int c = 0; c < 8; c++) s += part2[tid * 9 + c];
        PT[(size_t)blockIdx.x * Mn + m0 + tid] = s;
    }
}

// --------------------------- tail kernels ----------------------------------
__global__ void combine_k(const float* __restrict__ PT, const float* __restrict__ unb,
                          float* __restrict__ up, float* __restrict__ inx,
                          float* __restrict__ iny)
{
    const int r = blockIdx.x * 256 + threadIdx.x;
    float a = 0.f, b = 0.f, c = 0.f;
    #pragma unroll
    for (int nb = 0; nb < 12; nb++)  a += PT[(size_t)nb * Mn + r];
    #pragma unroll
    for (int nb = 12; nb < 24; nb++) b += PT[(size_t)nb * Mn + r];
    #pragma unroll
    for (int nb = 24; nb < 36; nb++) c += PT[(size_t)nb * Mn + r];
    up[r]  = a + unb[0];
    inx[r] = 1.f / fmaxf(sqrtf(b), 1e-12f);
    iny[r] = 1.f / fmaxf(sqrtf(c), 1e-12f);
}

// ybar partials: grid (6 colblocks, 8 t-slices, 32 batches) x 128
__global__ void ybar_part_k(const float* __restrict__ YE, const float* __restrict__ iny,
                            float* __restrict__ PTY)
{
    const int b = blockIdx.z, slice = blockIdx.y;
    const int col = blockIdx.x * 128 + threadIdx.x;
    const int t0 = slice * 128;
    const float* p = YE + ((size_t)b * 1024 + t0) * 768 + col;
    const float* w = iny + b * 1024 + t0;
    float s = 0.f;
    #pragma unroll 8
    for (int tt = 0; tt < 128; ++tt) s += p[(size_t)tt * 768] * w[tt];
    PTY[((size_t)(b * 8 + slice)) * 768 + col] = s;
}
// reduce 8 slices -> ybar   grid (32, 6) x 128
__global__ void ybar_red_k(const float* __restrict__ PTY, float* __restrict__ YB)
{
    const int b = blockIdx.x, col = blockIdx.y * 128 + threadIdx.x;
    float s = 0.f;
    #pragma unroll
    for (int sl = 0; sl < 8; sl++) s += PTY[((size_t)(b * 8 + sl)) * 768 + col];
    YB[b * 768 + col] = s * (1.0f / 1024.0f);
}

__global__ void scores_k(const float* __restrict__ XE, const float* __restrict__ YB,
                         const float* __restrict__ invnx, const float* __restrict__ unpot,
                         const float* __restrict__ redw, float* __restrict__ sc)
{
    __shared__ float red[8];
    const int r = blockIdx.x, tid = threadIdx.x;
    const int b = r >> 10;
    const size_t base = (size_t)r * 768;
    const float* yb = YB + b * 768;
    float d = XE[base + tid] * yb[tid]
            + XE[base + tid + 256] * yb[tid + 256]
            + XE[base + tid + 512] * yb[tid + 512];
    #pragma unroll
    for (int o = 16; o; o >>= 1) d += __shfl_xor_sync(0xffffffffu, d, o);
    if ((tid & 31) == 0) red[tid >> 5] = d;
    __syncthreads();
    if (tid == 0) {
        float D = 0.f;
        #pragma unroll
        for (int i = 0; i < 8; i++) D += red[i];
        sc[r] = redw[0] * unpot[r] + redw[1] * (D * invnx[r]);
    }
}

// softmax over T -> weights   grid 32 x 256
__global__ void softmax_k(const float* __restrict__ sc, float* __restrict__ WS)
{
    __shared__ float red[8];
    __shared__ float finv;
    const int b = blockIdx.x, tid = threadIdx.x;
    float l0 = sc[b * 1024 + tid];
    float l1 = sc[b * 1024 + tid + 256];
    float l2 = sc[b * 1024 + tid + 512];
    float l3 = sc[b * 1024 + tid + 768];
    float mx = fmaxf(fmaxf(l0, l1), fmaxf(l2, l3));
    #pragma unroll
    for (int o = 16; o; o >>= 1) mx = fmaxf(mx, __shfl_xor_sync(0xffffffffu, mx, o));
    if ((tid & 31) == 0) red[tid >> 5] = mx;
    __syncthreads();
    if (tid == 0) {
        float M = red[0];
        #pragma unroll
        for (int i = 1; i < 8; i++) M = fmaxf(M, red[i]);
        finv = M;
    }
    __syncthreads();
    const float M = finv;
    __syncthreads();
    l0 = expf(l0 - M); l1 = expf(l1 - M); l2 = expf(l2 - M); l3 = expf(l3 - M);
    float s = l0 + l1 + l2 + l3;
    #pragma unroll
    for (int o = 16; o; o >>= 1) s += __shfl_xor_sync(0xffffffffu, s, o);
    if ((tid & 31) == 0) red[tid >> 5] = s;
    __syncthreads();
    if (tid == 0) {
        float S = 0.f;
        #pragma unroll
        for (int i = 0; i < 8; i++) S += red[i];
        finv = 1.f / S;
    }
    __syncthreads();
    const float inv = finv;
    WS[b * 1024 + tid]       = l0 * inv;
    WS[b * 1024 + tid + 256] = l1 * inv;
    WS[b * 1024 + tid + 512] = l2 * inv;
    WS[b * 1024 + tid + 768] = l3 * inv;
}

// weighted-sum partials: grid (8 t-slices, 32 batches) x 256
__global__ void wsum_k(const float* __restrict__ U, const float* __restrict__ WS,
                       float* __restrict__ PTF)
{
    __shared__ float wsh[128];
    const int slice = blockIdx.x, b = blockIdx.y, tid = threadIdx.x;
    const int t0 = slice * 128;
    if (tid < 128) wsh[tid] = WS[b * 1024 + t0 + tid];
    __syncthreads();
    const float* Ub = U + ((size_t)b * 1024 + t0) * 768;
    float a0 = 0.f, a1 = 0.f, a2 = 0.f;
    #pragma unroll 4
    for (int tt = 0; tt < 128; ++tt) {
        const float wt = wsh[tt];
        const float* row = Ub + (size_t)tt * 768;
        a0 += wt * row[tid];
        a1 += wt * row[tid + 256];
        a2 += wt * row[tid + 512];
    }
    float* pf = PTF + ((size_t)(b * 8 + slice)) * 768;
    pf[tid] = a0; pf[tid + 256] = a1; pf[tid + 512] = a2;
}
// reduce 8 slices -> out   grid 32 x 256
__global__ void wred_k(const float* __restrict__ PTF, float* __restrict__ out)
{
    const int b = blockIdx.x, tid = threadIdx.x;
    #pragma unroll
    for (int cblk = 0; cblk < 3; cblk++) {
        const int c = tid + cblk * 256;
        float s = 0.f;
        #pragma unroll
        for (int sl = 0; sl < 8; sl++) s += PTF[((size_t)(b * 8 + sl)) * 768 + c];
        out[b * 768 + c] = s;
    }
}

// ---------------------------------------------------------------------------
extern "C" void kernel_launch(void* const* d_in, const int* in_sizes, int n_in,
                              void* d_out, int out_size)
{
    (void)in_sizes; (void)n_in; (void)out_size;
    const float* x        = (const float*)d_in[0];
    const float* fc1_b    = (const float*)d_in[2];
    const float* fc2_b    = (const float*)d_in[4];
    const float* un_emb_b = (const float*)d_in[6];
    const float* un_red_w = (const float*)d_in[7];
    const float* un_red_b = (const float*)d_in[8];
    const float* pw_x_b   = (const float*)d_in[10];
    const float* pw_y_b   = (const float*)d_in[12];
    const float* red_w    = (const float*)d_in[13];
    float* out = (float*)d_out;

    float *H, *U, *XE, *YE, *W1, *W2, *Wc, *PT, *PTY, *PTF, *WS, *YB, *UP, *INX, *INY, *SC;
    cudaGetSymbolAddress((void**)&H,   g_H);
    cudaGetSymbolAddress((void**)&U,   g_U);
    cudaGetSymbolAddress((void**)&XE,  g_XE);
    cudaGetSymbolAddress((void**)&YE,  g_YE);
    cudaGetSymbolAddress((void**)&W1,  g_W1);
    cudaGetSymbolAddress((void**)&W2,  g_W2);
    cudaGetSymbolAddress((void**)&Wc,  g_Wc);
    cudaGetSymbolAddress((void**)&PT,  g_PT);
    cudaGetSymbolAddress((void**)&PTY, g_PTY);
    cudaGetSymbolAddress((void**)&PTF, g_PTF);
    cudaGetSymbolAddress((void**)&WS,  g_WS);
    cudaGetSymbolAddress((void**)&YB,  g_YB);
    cudaGetSymbolAddress((void**)&UP,  g_UP);
    cudaGetSymbolAddress((void**)&INX, g_INX);
    cudaGetSymbolAddress((void**)&INY, g_INY);
    cudaGetSymbolAddress((void**)&SC,  g_SC);

    cudaFuncSetAttribute((const void*)gemm_tf32<true,  true >, cudaFuncAttributeMaxDynamicSharedMemorySize, GSMEM);
    cudaFuncSetAttribute((const void*)gemm_tf32<false, true >, cudaFuncAttributeMaxDynamicSharedMemorySize, GSMEM);
    cudaFuncSetAttribute((const void*)gemm_fused3, cudaFuncAttributeMaxDynamicSharedMemorySize, GSMEM);

    // round the 5 weight matrices (x fed raw: HW tf32 truncation on A operand)
    {
        RoundBatch rb;
        const int n1 = INn * INn / 4, n2 = Dn * INn / 4, n3 = Dn * Dn / 4;
        rb.s[0] = (const float4*)d_in[1];  rb.d[0] = (float4*)W1;
        rb.s[1] = (const float4*)d_in[3];  rb.d[1] = (float4*)W2;
        rb.s[2] = (const float4*)d_in[5];  rb.d[2] = (float4*)Wc;
        rb.s[3] = (const float4*)d_in[9];  rb.d[3] = (float4*)(Wc + (size_t)Dn * Dn);
        rb.s[4] = (const float4*)d_in[11]; rb.d[4] = (float4*)(Wc + (size_t)2 * Dn * Dn);
        rb.off[0] = 0; rb.off[1] = n1; rb.off[2] = n1 + n2;
        rb.off[3] = rb.off[2] + n3; rb.off[4] = rb.off[3] + n3; rb.off[5] = rb.off[4] + n3;
        round_batch_k<<<(rb.off[5] + 255) / 256, 256>>>(rb);
    }

    // 1. H = round(relu(x @ W1^T + b))   [32768 x 1536], K=1536  (x raw)
    gemm_tf32<true, true><<<dim3(24, 256), 128, GSMEM>>>(x, W1, fc1_b, H, 1536, 1536);
    // 2. U = round(H @ W2^T + b)         [32768 x 768], K=1536
    gemm_tf32<false, true><<<dim3(12, 256), 128, GSMEM>>>(H, W2, fc2_b, U, 768, 1536);
    // 3. fused E|XE|YE                   [32768 x 2304], K=768; E never stored
    gemm_fused3<<<dim3(36, 256), 128, GSMEM>>>(U, Wc, un_emb_b, pw_x_b, pw_y_b,
                                               un_red_w, XE, YE, PT);
    // 4-9. combine, ybar (split), scores, softmax, weighted sum (split)
    combine_k<<<Mn / 256, 256>>>(PT, un_red_b, UP, INX, INY);
    ybar_part_k<<<dim3(6, 8, Bn), 128>>>(YE, INY, PTY);
    ybar_red_k<<<dim3(Bn, 6), 128>>>(PTY, YB);
    scores_k<<<Mn, 256>>>(XE, YB, INX, UP, red_w, SC);
    softmax_k<<<Bn, 256>>>(SC, WS);
    wsum_k<<<dim3(8, Bn), 256>>>(U, WS, PTF);
    wred_k<<<Bn, 256>>>(PTF, out);
}

// round 14
// speedup vs baseline: 3.1816x; 1.6821x over previous
#include <cuda_runtime.h>
#include <cuda_fp16.h>
#include <cstdint>
#include <cstddef>

namespace {
constexpr int Bn = 32, Tn = 1024, INn = 1536, Dn = 768;
constexpr int Mn = Bn * Tn;  // 32768
constexpr int GSMEM = 48 * 1024;  // 2 stages x (A 16KB + B 8KB), fp16 K-tile 64
}

// Scratch (static __device__ globals: allocation-free rule)
__device__ __align__(256) __half g_Xh[(size_t)Mn * INn];
__device__ __align__(256) __half g_Hh[(size_t)Mn * INn];
__device__ __align__(256) float  g_U [(size_t)Mn * Dn];
__device__ __align__(256) __half g_Uh[(size_t)Mn * Dn];
__device__ __align__(256) float  g_XE[(size_t)Mn * Dn];
__device__ __align__(256) float  g_YE[(size_t)Mn * Dn];
__device__ __align__(256) __half g_W1[(size_t)INn * INn];
__device__ __align__(256) __half g_W2[(size_t)Dn * INn];
__device__ __align__(256) __half g_Wc[(size_t)3 * Dn * Dn];
__device__ __align__(256) float  g_PT[(size_t)36 * Mn];
__device__ __align__(256) float  g_PTY[(size_t)Bn * 8 * Dn];
__device__ __align__(256) float  g_PTF[(size_t)Bn * 8 * Dn];
__device__ __align__(256) float  g_WS[Mn];
__device__ __align__(256) float  g_YB[Bn * Dn];
__device__ __align__(256) float  g_UP[Mn];
__device__ __align__(256) float  g_INX[Mn];
__device__ __align__(256) float  g_INY[Mn];
__device__ __align__(256) float  g_SC[Mn];

// ---------------------------------------------------------------------------
// helpers
// ---------------------------------------------------------------------------
__device__ __forceinline__ uint32_t smem_u32(const void* p) {
    uint32_t a;
    asm("{ .reg .u64 t; cvta.to.shared.u64 t, %1; cvt.u32.u64 %0, t; }" : "=r"(a) : "l"(p));
    return a;
}
__device__ __forceinline__ void cp16(void* s, const void* g) {
    uint32_t sa = (uint32_t)__cvta_generic_to_shared(s);
    asm volatile("cp.async.cg.shared.global [%0], [%1], 16;\n" :: "r"(sa), "l"(g));
}
__device__ __forceinline__ void cp_commit() { asm volatile("cp.async.commit_group;\n"); }
template <int NW> __device__ __forceinline__ void cp_wait() {
    asm volatile("cp.async.wait_group %0;\n" :: "n"(NW));
}
// fp16 m16n8k16, fp32 accumulate
__device__ __forceinline__ void mma16(float* c, const uint32_t* a, const uint32_t* b) {
    asm volatile(
        "mma.sync.aligned.m16n8k16.row.col.f32.f16.f16.f32 "
        "{%0,%1,%2,%3}, {%4,%5,%6,%7}, {%8,%9}, {%0,%1,%2,%3};\n"
        : "+f"(c[0]), "+f"(c[1]), "+f"(c[2]), "+f"(c[3])
        : "r"(a[0]), "r"(a[1]), "r"(a[2]), "r"(a[3]), "r"(b[0]), "r"(b[1]));
}
__device__ __forceinline__ void ldsm4(uint32_t* r, uint32_t addr) {
    asm volatile("ldmatrix.sync.aligned.m8n8.x4.shared.b16 {%0,%1,%2,%3}, [%4];"
                 : "=r"(r[0]), "=r"(r[1]), "=r"(r[2]), "=r"(r[3]) : "r"(addr));
}
__device__ __forceinline__ void ldsm2(uint32_t* r, uint32_t addr) {
    asm volatile("ldmatrix.sync.aligned.m8n8.x2.shared.b16 {%0,%1}, [%2];"
                 : "=r"(r[0]), "=r"(r[1]) : "r"(addr));
}

// x -> fp16 (rn)
__global__ void cvt_x_k(const float4* __restrict__ src, __half* __restrict__ dst, int n4)
{
    int i = blockIdx.x * 256 + threadIdx.x;
    if (i >= n4) return;
    float4 v = src[i];
    __half2* d = (__half2*)(dst + (size_t)i * 4);
    d[0] = __floats2half2_rn(v.x, v.y);
    d[1] = __floats2half2_rn(v.z, v.w);
}
struct CvtBatch { const float4* s[5]; __half* d[5]; int off[6]; };
__global__ void cvt_batch_k(CvtBatch cb)
{
    int i = blockIdx.x * 256 + threadIdx.x;
    #pragma unroll
    for (int j = 0; j < 5; j++) {
        if (i >= cb.off[j] && i < cb.off[j + 1]) {
            int k = i - cb.off[j];
            float4 v = cb.s[j][k];
            __half2* d = (__half2*)(cb.d[j] + (size_t)k * 4);
            d[0] = __floats2half2_rn(v.x, v.y);
            d[1] = __floats2half2_rn(v.z, v.w);
        }
    }
}

// ---------------------------------------------------------------------------
// fp16 GEMM core: CTA 128(M)x64(N)x64(K), 128 threads, 4 warps 2x2, warp tile
// 64x32, m16n8k16 via ldmatrix (identical 16B-unit swizzle geometry to the
// verified tf32 core), 2-stage dual-sync cp.async pipeline, 4 CTAs/SM.
// SMEM halves: A stage s at s*8192 (16KB), B stage s at 16384+s*4096 (8KB).
// Rows are 64 halves = 128 bytes. K%64==0.
// ---------------------------------------------------------------------------
#define GEMM16_PRE_MAIN(APTR, WPTR, KVAL)                                               \
    extern __shared__ __half smh[];                                                     \
    const int tid  = threadIdx.x;                                                       \
    const int lane = tid & 31, wrp = tid >> 5;                                          \
    const int wm = wrp >> 1, wn = wrp & 1;                                              \
    const int m0 = blockIdx.y * 128, n0 = blockIdx.x * 64;                              \
    const int c4 = tid & 7, rb = tid >> 3;                                              \
    const int soff = rb * 64 + ((c4 ^ (rb & 7)) << 3);                                  \
    const __half* gA = (APTR) + (size_t)(m0 + rb) * (KVAL) + c4 * 8;                    \
    const __half* gW = (WPTR) + (size_t)(n0 + rb) * (KVAL) + c4 * 8;                    \
    const uint32_t smb = smem_u32(smh);                                                 \
    const int s7 = lane & 7;                                                            \
    const int half8 = (lane >> 3) & 1;                                                  \
    const int koffA = lane >> 4;                                                        \
    const int koffB = (lane >> 3) & 1;                                                  \
    uint32_t rowA[4], rowB[4];                                                          \
    _Pragma("unroll")                                                                   \
    for (int mf = 0; mf < 4; mf++)                                                      \
        rowA[mf] = (uint32_t)(wm * 64 + mf * 16 + half8 * 8 + s7) * 128u;               \
    _Pragma("unroll")                                                                   \
    for (int nf = 0; nf < 4; nf++)                                                      \
        rowB[nf] = (uint32_t)(wn * 32 + nf * 8 + s7) * 128u;                            \
    float acc[4][4][4];                                                                 \
    _Pragma("unroll")                                                                   \
    for (int i = 0; i < 4; i++)                                                         \
        _Pragma("unroll")                                                               \
        for (int j = 0; j < 4; j++)                                                     \
            _Pragma("unroll")                                                           \
            for (int q = 0; q < 4; q++) acc[i][j][q] = 0.f;                             \
    const int kiters = (KVAL) >> 6;                                                     \
    _Pragma("unroll")                                                                   \
    for (int p = 0; p < 8; p++) cp16(&smh[soff + p * 1024], gA + (size_t)p * 16 * (KVAL)); \
    _Pragma("unroll")                                                                   \
    for (int p = 0; p < 4; p++) cp16(&smh[16384 + soff + p * 1024], gW + (size_t)p * 16 * (KVAL)); \
    cp_commit();                                                                        \
    for (int it = 0; it < kiters; ++it) {                                               \
        const int st = it & 1;                                                          \
        if (it + 1 < kiters) {                                                          \
            const int k0  = (it + 1) << 6;                                              \
            const int stn = (it + 1) & 1;                                               \
            _Pragma("unroll")                                                           \
            for (int p = 0; p < 8; p++)                                                 \
                cp16(&smh[stn * 8192 + soff + p * 1024], gA + k0 + (size_t)p * 16 * (KVAL)); \
            _Pragma("unroll")                                                           \
            for (int p = 0; p < 4; p++)                                                 \
                cp16(&smh[16384 + stn * 4096 + soff + p * 1024], gW + k0 + (size_t)p * 16 * (KVAL)); \
            cp_commit();                                                                \
            cp_wait<1>();                                                               \
        } else {                                                                        \
            cp_wait<0>();                                                               \
        }                                                                               \
        __syncthreads();                                                                \
        const uint32_t stA = smb + (uint32_t)st * 16384u;                               \
        const uint32_t stB = smb + 32768u + (uint32_t)st * 8192u;                       \
        _Pragma("unroll")                                                               \
        for (int kk = 0; kk < 8; kk += 2) {                                             \
            const uint32_t colA = (uint32_t)(((kk + koffA) ^ s7) << 4);                 \
            const uint32_t colB = (uint32_t)(((kk + koffB) ^ s7) << 4);                 \
            uint32_t af[4][4], bf[4][2];                                                \
            _Pragma("unroll")                                                           \
            for (int mf = 0; mf < 4; mf++) ldsm4(af[mf], stA + rowA[mf] + colA);        \
            _Pragma("unroll")                                                           \
            for (int nf = 0; nf < 4; nf++) ldsm2(bf[nf], stB + rowB[nf] + colB);        \
            _Pragma("unroll")                                                           \
            for (int mf = 0; mf < 4; mf++)                                              \
                _Pragma("unroll")                                                       \
                for (int nf = 0; nf < 4; nf++)                                          \
                    mma16(acc[mf][nf], af[mf], bf[nf]);                                 \
        }                                                                               \
        __syncthreads();                                                                \
    }

// MODE 1: fp16 output only (fc1 -> H). MODE 2: dual fp32 + fp16 (fc2 -> U,Uh).
template <bool RELU, int MODE>
__global__ __launch_bounds__(128, 4) void gemm_fp16(
    const __half* __restrict__ A, const __half* __restrict__ W,
    const float* __restrict__ bias, float* __restrict__ C,
    __half* __restrict__ Ch, int N, int K)
{
    GEMM16_PRE_MAIN(A, W, K)

    const int g = lane >> 2, t = lane & 3;
    #pragma unroll
    for (int mf = 0; mf < 4; mf++) {
        const int row = m0 + wm * 64 + mf * 16 + g;
        #pragma unroll
        for (int nf = 0; nf < 4; nf++) {
            const int col = n0 + wn * 32 + nf * 8 + 2 * t;
            const float b0 = bias[col], b1 = bias[col + 1];
            float v0 = acc[mf][nf][0] + b0;
            float v1 = acc[mf][nf][1] + b1;
            float v2 = acc[mf][nf][2] + b0;
            float v3 = acc[mf][nf][3] + b1;
            if (RELU) {
                v0 = fmaxf(v0, 0.f); v1 = fmaxf(v1, 0.f);
                v2 = fmaxf(v2, 0.f); v3 = fmaxf(v3, 0.f);
            }
            if (MODE == 2) {
                *(float2*)(C + (size_t)row       * N + col) = make_float2(v0, v1);
                *(float2*)(C + (size_t)(row + 8) * N + col) = make_float2(v2, v3);
            }
            *(__half2*)(Ch + (size_t)row       * N + col) = __floats2half2_rn(v0, v1);
            *(__half2*)(Ch + (size_t)(row + 8) * N + col) = __floats2half2_rn(v2, v3);
        }
    }
}

// Fused D-GEMM (fp16 operands): N=2304 concat [E | XE | YE]; 36 n-blocks.
__global__ __launch_bounds__(128, 4) void gemm_fused3(
    const __half* __restrict__ A, const __half* __restrict__ W,
    const float* __restrict__ b_e, const float* __restrict__ b_x,
    const float* __restrict__ b_y, const float* __restrict__ unred,
    float* __restrict__ XE, float* __restrict__ YE, float* __restrict__ PT)
{
    GEMM16_PRE_MAIN(A, W, 768)

    const int g = lane >> 2, t = lane & 3;
    const int seg = blockIdx.x / 12;             // 0:E 1:XE 2:YE
    const float* bias = (seg == 0) ? b_e : (seg == 1) ? b_x : b_y;
    float* Cseg = (seg == 1) ? XE : YE;
    const int cb0 = (blockIdx.x - seg * 12) * 64 + wn * 32;

    float* part2 = (float*)smh;   // mainloop ended with __syncthreads: stages dead

    #pragma unroll
    for (int mf = 0; mf < 4; mf++) {
        const int row = wm * 64 + mf * 16 + g;
        float ps0 = 0.f, ps1 = 0.f;
        #pragma unroll
        for (int nf = 0; nf < 4; nf++) {
            const int cs = cb0 + nf * 8 + 2 * t;
            const float b0 = bias[cs], b1 = bias[cs + 1];
            float v0 = acc[mf][nf][0] + b0;
            float v1 = acc[mf][nf][1] + b1;
            float v2 = acc[mf][nf][2] + b0;
            float v3 = acc[mf][nf][3] + b1;
            if (seg == 0) {
                v0 = fmaxf(v0, 0.f); v1 = fmaxf(v1, 0.f);
                v2 = fmaxf(v2, 0.f); v3 = fmaxf(v3, 0.f);
                const float w0 = unred[cs], w1 = unred[cs + 1];
                ps0 += v0 * w0 + v1 * w1;
                ps1 += v2 * w0 + v3 * w1;
            } else {
                ps0 += v0 * v0 + v1 * v1;
                ps1 += v2 * v2 + v3 * v3;
                *(float2*)(Cseg + (size_t)(m0 + row)     * 768 + cs) = make_float2(v0, v1);
                *(float2*)(Cseg + (size_t)(m0 + row + 8) * 768 + cs) = make_float2(v2, v3);
            }
        }
        part2[row * 9 + wn * 4 + t]       = ps0;
        part2[(row + 8) * 9 + wn * 4 + t] = ps1;
    }
    __syncthreads();
    if (tid < 128) {
        float s = 0.f;
        #pragma unroll
        for (int c = 0; c < 8; c++) s += part2[tid * 9 + c];
        PT[(size_t)blockIdx.x * Mn + m0 + tid] = s;
    }
}

// --------------------------- tail kernels ----------------------------------
__global__ void combine_k(const float* __restrict__ PT, const float* __restrict__ unb,
                          float* __restrict__ up, float* __restrict__ inx,
                          float* __restrict__ iny)
{
    const int r = blockIdx.x * 256 + threadIdx.x;
    float a = 0.f, b = 0.f, c = 0.f;
    #pragma unroll
    for (int nb = 0; nb < 12; nb++)  a += PT[(size_t)nb * Mn + r];
    #pragma unroll
    for (int nb = 12; nb < 24; nb++) b += PT[(size_t)nb * Mn + r];
    #pragma unroll
    for (int nb = 24; nb < 36; nb++) c += PT[(size_t)nb * Mn + r];
    up[r]  = a + unb[0];
    inx[r] = 1.f / fmaxf(sqrtf(b), 1e-12f);
    iny[r] = 1.f / fmaxf(sqrtf(c), 1e-12f);
}

__global__ void ybar_part_k(const float* __restrict__ YE, const float* __restrict__ iny,
                            float* __restrict__ PTY)
{
    const int b = blockIdx.z, slice = blockIdx.y;
    const int col = blockIdx.x * 128 + threadIdx.x;
    const int t0 = slice * 128;
    const float* p = YE + ((size_t)b * 1024 + t0) * 768 + col;
    const float* w = iny + b * 1024 + t0;
    float s = 0.f;
    #pragma unroll 8
    for (int tt = 0; tt < 128; ++tt) s += p[(size_t)tt * 768] * w[tt];
    PTY[((size_t)(b * 8 + slice)) * 768 + col] = s;
}
__global__ void ybar_red_k(const float* __restrict__ PTY, float* __restrict__ YB)
{
    const int b = blockIdx.x, col = blockIdx.y * 128 + threadIdx.x;
    float s = 0.f;
    #pragma unroll
    for (int sl = 0; sl < 8; sl++) s += PTY[((size_t)(b * 8 + sl)) * 768 + col];
    YB[b * 768 + col] = s * (1.0f / 1024.0f);
}

__global__ void scores_k(const float* __restrict__ XE, const float* __restrict__ YB,
                         const float* __restrict__ invnx, const float* __restrict__ unpot,
                         const float* __restrict__ redw, float* __restrict__ sc)
{
    __shared__ float red[8];
    const int r = blockIdx.x, tid = threadIdx.x;
    const int b = r >> 10;
    const size_t base = (size_t)r * 768;
    const float* yb = YB + b * 768;
    float d = XE[base + tid] * yb[tid]
            + XE[base + tid + 256] * yb[tid + 256]
            + XE[base + tid + 512] * yb[tid + 512];
    #pragma unroll
    for (int o = 16; o; o >>= 1) d += __shfl_xor_sync(0xffffffffu, d, o);
    if ((tid & 31) == 0) red[tid >> 5] = d;
    __syncthreads();
    if (tid == 0) {
        float D = 0.f;
        #pragma unroll
        for (int i = 0; i < 8; i++) D += red[i];
        sc[r] = redw[0] * unpot[r] + redw[1] * (D * invnx[r]);
    }
}

__global__ void softmax_k(const float* __restrict__ sc, float* __restrict__ WS)
{
    __shared__ float red[8];
    __shared__ float finv;
    const int b = blockIdx.x, tid = threadIdx.x;
    float l0 = sc[b * 1024 + tid];
    float l1 = sc[b * 1024 + tid + 256];
    float l2 = sc[b * 1024 + tid + 512];
    float l3 = sc[b * 1024 + tid + 768];
    float mx = fmaxf(fmaxf(l0, l1), fmaxf(l2, l3));
    #pragma unroll
    for (int o = 16; o; o >>= 1) mx = fmaxf(mx, __shfl_xor_sync(0xffffffffu, mx, o));
    if ((tid & 31) == 0) red[tid >> 5] = mx;
    __syncthreads();
    if (tid == 0) {
        float M = red[0];
        #pragma unroll
        for (int i = 1; i < 8; i++) M = fmaxf(M, red[i]);
        finv = M;
    }
    __syncthreads();
    const float M = finv;
    __syncthreads();
    l0 = expf(l0 - M); l1 = expf(l1 - M); l2 = expf(l2 - M); l3 = expf(l3 - M);
    float s = l0 + l1 + l2 + l3;
    #pragma unroll
    for (int o = 16; o; o >>= 1) s += __shfl_xor_sync(0xffffffffu, s, o);
    if ((tid & 31) == 0) red[tid >> 5] = s;
    __syncthreads();
    if (tid == 0) {
        float S = 0.f;
        #pragma unroll
        for (int i = 0; i < 8; i++) S += red[i];
        finv = 1.f / S;
    }
    __syncthreads();
    const float inv = finv;
    WS[b * 1024 + tid]       = l0 * inv;
    WS[b * 1024 + tid + 256] = l1 * inv;
    WS[b * 1024 + tid + 512] = l2 * inv;
    WS[b * 1024 + tid + 768] = l3 * inv;
}

__global__ void wsum_k(const float* __restrict__ U, const float* __restrict__ WS,
                       float* __restrict__ PTF)
{
    __shared__ float wsh[128];
    const int slice = blockIdx.x, b = blockIdx.y, tid = threadIdx.x;
    const int t0 = slice * 128;
    if (tid < 128) wsh[tid] = WS[b * 1024 + t0 + tid];
    __syncthreads();
    const float* Ub = U + ((size_t)b * 1024 + t0) * 768;
    float a0 = 0.f, a1 = 0.f, a2 = 0.f;
    #pragma unroll 4
    for (int tt = 0; tt < 128; ++tt) {
        const float wt = wsh[tt];
        const float* row = Ub + (size_t)tt * 768;
        a0 += wt * row[tid];
        a1 += wt * row[tid + 256];
        a2 += wt * row[tid + 512];
    }
    float* pf = PTF + ((size_t)(b * 8 + slice)) * 768;
    pf[tid] = a0; pf[tid + 256] = a1; pf[tid + 512] = a2;
}
__global__ void wred_k(const float* __restrict__ PTF, float* __restrict__ out)
{
    const int b = blockIdx.x, tid = threadIdx.x;
    #pragma unroll
    for (int cblk = 0; cblk < 3; cblk++) {
        const int c = tid + cblk * 256;
        float s = 0.f;
        #pragma unroll
        for (int sl = 0; sl < 8; sl++) s += PTF[((size_t)(b * 8 + sl)) * 768 + c];
        out[b * 768 + c] = s;
    }
}

// ---------------------------------------------------------------------------
extern "C" void kernel_launch(void* const* d_in, const int* in_sizes, int n_in,
                              void* d_out, int out_size)
{
    (void)in_sizes; (void)n_in; (void)out_size;
    const float* x        = (const float*)d_in[0];
    const float* fc1_b    = (const float*)d_in[2];
    const float* fc2_b    = (const float*)d_in[4];
    const float* un_emb_b = (const float*)d_in[6];
    const float* un_red_w = (const float*)d_in[7];
    const float* un_red_b = (const float*)d_in[8];
    const float* pw_x_b   = (const float*)d_in[10];
    const float* pw_y_b   = (const float*)d_in[12];
    const float* red_w    = (const float*)d_in[13];
    float* out = (float*)d_out;

    __half *Xh, *Hh, *Uh, *W1, *W2, *Wc;
    float *U, *XE, *YE, *PT, *PTY, *PTF, *WS, *YB, *UP, *INX, *INY, *SC;
    cudaGetSymbolAddress((void**)&Xh,  g_Xh);
    cudaGetSymbolAddress((void**)&Hh,  g_Hh);
    cudaGetSymbolAddress((void**)&U,   g_U);
    cudaGetSymbolAddress((void**)&Uh,  g_Uh);
    cudaGetSymbolAddress((void**)&XE,  g_XE);
    cudaGetSymbolAddress((void**)&YE,  g_YE);
    cudaGetSymbolAddress((void**)&W1,  g_W1);
    cudaGetSymbolAddress((void**)&W2,  g_W2);
    cudaGetSymbolAddress((void**)&Wc,  g_Wc);
    cudaGetSymbolAddress((void**)&PT,  g_PT);
    cudaGetSymbolAddress((void**)&PTY, g_PTY);
    cudaGetSymbolAddress((void**)&PTF, g_PTF);
    cudaGetSymbolAddress((void**)&WS,  g_WS);
    cudaGetSymbolAddress((void**)&YB,  g_YB);
    cudaGetSymbolAddress((void**)&UP,  g_UP);
    cudaGetSymbolAddress((void**)&INX, g_INX);
    cudaGetSymbolAddress((void**)&INY, g_INY);
    cudaGetSymbolAddress((void**)&SC,  g_SC);

    cudaFuncSetAttribute((const void*)gemm_fp16<true, 1>,  cudaFuncAttributeMaxDynamicSharedMemorySize, GSMEM);
    cudaFuncSetAttribute((const void*)gemm_fp16<false, 2>, cudaFuncAttributeMaxDynamicSharedMemorySize, GSMEM);
    cudaFuncSetAttribute((const void*)gemm_fused3, cudaFuncAttributeMaxDynamicSharedMemorySize, GSMEM);

    // convert x + all weights to fp16 (rn)
    cvt_x_k<<<Mn * INn / 4 / 256, 256>>>((const float4*)x, Xh, Mn * INn / 4);
    {
        CvtBatch cb;
        const int n1 = INn * INn / 4, n2 = Dn * INn / 4, n3 = Dn * Dn / 4;
        cb.s[0] = (const float4*)d_in[1];  cb.d[0] = W1;
        cb.s[1] = (const float4*)d_in[3];  cb.d[1] = W2;
        cb.s[2] = (const float4*)d_in[5];  cb.d[2] = Wc;
        cb.s[3] = (const float4*)d_in[9];  cb.d[3] = Wc + (size_t)Dn * Dn;
        cb.s[4] = (const float4*)d_in[11]; cb.d[4] = Wc + (size_t)2 * Dn * Dn;
        cb.off[0] = 0; cb.off[1] = n1; cb.off[2] = n1 + n2;
        cb.off[3] = cb.off[2] + n3; cb.off[4] = cb.off[3] + n3; cb.off[5] = cb.off[4] + n3;
        cvt_batch_k<<<(cb.off[5] + 255) / 256, 256>>>(cb);
    }

    // 1. Hh = fp16(relu(Xh @ W1^T + b))   [32768 x 1536], K=1536
    gemm_fp16<true, 1><<<dim3(24, 256), 128, GSMEM>>>(Xh, W1, fc1_b, nullptr, Hh, 1536, 1536);
    // 2. U (fp32) + Uh (fp16) = Hh @ W2^T + b   [32768 x 768], K=1536
    gemm_fp16<false, 2><<<dim3(12, 256), 128, GSMEM>>>(Hh, W2, fc2_b, U, Uh, 768, 1536);
    // 3. fused E|XE|YE from Uh            [32768 x 2304], K=768; E never stored
    gemm_fused3<<<dim3(36, 256), 128, GSMEM>>>(Uh, Wc, un_emb_b, pw_x_b, pw_y_b,
                                               un_red_w, XE, YE, PT);
    // 4-9. combine, ybar (split), scores, softmax, weighted sum (split)
    combine_k<<<Mn / 256, 256>>>(PT, un_red_b, UP, INX, INY);
    ybar_part_k<<<dim3(6, 8, Bn), 128>>>(YE, INY, PTY);
    ybar_red_k<<<dim3(Bn, 6), 128>>>(PTY, YB);
    scores_k<<<Mn, 256>>>(XE, YB, INX, UP, red_w, SC);
    softmax_k<<<Bn, 256>>>(SC, WS);
    wsum_k<<<dim3(8, Bn), 256>>>(U, WS, PTF);
    wred_k<<<Bn, 256>>>(PTF, out);
}